// round 3
// baseline (speedup 1.0000x reference)
#include <cuda_runtime.h>
#include <math.h>

#define Bv 2
#define Tv 2048
#define Dv 1024
#define Hv 16
#define HDv 64
#define Mv (Bv * Tv)   // 4096

typedef unsigned long long u64;

// ---- f32x2 packed-math helpers (sm_100+ FFMA2 path; ptxas never auto-fuses) ----
__device__ __forceinline__ u64 pk2(float lo, float hi) {
    u64 r; asm("mov.b64 %0, {%1, %2};" : "=l"(r) : "f"(lo), "f"(hi)); return r;
}
__device__ __forceinline__ void upk2(float& lo, float& hi, u64 v) {
    asm("mov.b64 {%0, %1}, %2;" : "=f"(lo), "=f"(hi) : "l"(v));
}
__device__ __forceinline__ u64 fma2(u64 a, u64 b, u64 c) {
    u64 d; asm("fma.rn.f32x2 %0, %1, %2, %3;" : "=l"(d) : "l"(a), "l"(b), "l"(c)); return d;
}
__device__ __forceinline__ u64 mul2(u64 a, u64 b) {
    u64 d; asm("mul.rn.f32x2 %0, %1, %2;" : "=l"(d) : "l"(a), "l"(b)); return d;
}
__device__ __forceinline__ u64 add2(u64 a, u64 b) {
    u64 d; asm("add.rn.f32x2 %0, %1, %2;" : "=l"(d) : "l"(a), "l"(b)); return d;
}

// Scratch (allocation-free rule: __device__ globals)
__device__ float g_Q[Bv * Hv * Tv * HDv];   // [b,h,t,hd]
__device__ float g_K[Bv * Hv * Tv * HDv];
__device__ float g_V[Bv * Hv * Tv * HDv];
__device__ float g_AO[Bv * Tv * Dv];        // attention out, [b,t,h*HD+hd]
__device__ float g_QS[Bv * Hv * Tv * 3];
__device__ float g_CKV[Bv * Hv * Tv * 3];

// ---------------------------------------------------------------------------
// GEMM: C[m,n] = sum_k X[m,k] * W[n,k] + bias[n]
// M=4096, N=1024, K=1024. BM=BN=128, BK=16. 256 threads, 8x8 micro-tile,
// f32x2 packed FMA (pairs over m). Register-prefetched gmem loads.
// ---------------------------------------------------------------------------
template <bool SPLIT>
__global__ __launch_bounds__(256) void gemm_proj(const float* __restrict__ X,
                                                 const float* __restrict__ W,
                                                 const float* __restrict__ bias,
                                                 float* __restrict__ out) {
    __shared__ float As[16][128];   // As[k][m]
    __shared__ float Bs[16][128];   // Bs[k][n]

    const int K = 1024;
    const int n0 = blockIdx.x * 128;
    const int m0 = blockIdx.y * 128;
    const int tid = threadIdx.x;
    const int tx = tid & 15;       // 0..15 -> n micro-tile
    const int ty = tid >> 4;       // 0..15 -> m micro-tile

    // load indices: 512 float4 per matrix per tile step; 2 per thread
    const int r0 = tid >> 2,          cq0 = (tid & 3) * 4;
    const int r1 = (tid + 256) >> 2,  cq1 = ((tid + 256) & 3) * 4;

    u64 acc2[4][8];
#pragma unroll
    for (int i = 0; i < 4; i++)
#pragma unroll
        for (int j = 0; j < 8; j++) acc2[i][j] = 0ull;

    // preload first tile directly to smem
    {
        float4 a0 = *(const float4*)&X[(size_t)(m0 + r0) * K + cq0];
        float4 a1 = *(const float4*)&X[(size_t)(m0 + r1) * K + cq1];
        float4 b0 = *(const float4*)&W[(size_t)(n0 + r0) * K + cq0];
        float4 b1 = *(const float4*)&W[(size_t)(n0 + r1) * K + cq1];
        As[cq0 + 0][r0] = a0.x; As[cq0 + 1][r0] = a0.y; As[cq0 + 2][r0] = a0.z; As[cq0 + 3][r0] = a0.w;
        As[cq1 + 0][r1] = a1.x; As[cq1 + 1][r1] = a1.y; As[cq1 + 2][r1] = a1.z; As[cq1 + 3][r1] = a1.w;
        Bs[cq0 + 0][r0] = b0.x; Bs[cq0 + 1][r0] = b0.y; Bs[cq0 + 2][r0] = b0.z; Bs[cq0 + 3][r0] = b0.w;
        Bs[cq1 + 0][r1] = b1.x; Bs[cq1 + 1][r1] = b1.y; Bs[cq1 + 2][r1] = b1.z; Bs[cq1 + 3][r1] = b1.w;
    }
    __syncthreads();

    for (int k0 = 0; k0 < K; k0 += 16) {
        float4 pa0, pa1, pb0, pb1;
        const bool more = (k0 + 16) < K;
        if (more) {
            int kn = k0 + 16;
            pa0 = *(const float4*)&X[(size_t)(m0 + r0) * K + kn + cq0];
            pa1 = *(const float4*)&X[(size_t)(m0 + r1) * K + kn + cq1];
            pb0 = *(const float4*)&W[(size_t)(n0 + r0) * K + kn + cq0];
            pb1 = *(const float4*)&W[(size_t)(n0 + r1) * K + kn + cq1];
        }

#pragma unroll
        for (int kk = 0; kk < 16; kk++) {
            const u64* arow = (const u64*)&As[kk][ty * 8];
            u64 a2[4];
#pragma unroll
            for (int i = 0; i < 4; i++) a2[i] = arow[i];
            float4 bA = *(const float4*)&Bs[kk][tx * 8];
            float4 bB = *(const float4*)&Bs[kk][tx * 8 + 4];
            u64 bd[8];
            bd[0] = pk2(bA.x, bA.x); bd[1] = pk2(bA.y, bA.y);
            bd[2] = pk2(bA.z, bA.z); bd[3] = pk2(bA.w, bA.w);
            bd[4] = pk2(bB.x, bB.x); bd[5] = pk2(bB.y, bB.y);
            bd[6] = pk2(bB.z, bB.z); bd[7] = pk2(bB.w, bB.w);
#pragma unroll
            for (int i = 0; i < 4; i++)
#pragma unroll
                for (int j = 0; j < 8; j++) acc2[i][j] = fma2(a2[i], bd[j], acc2[i][j]);
        }
        __syncthreads();

        if (more) {
            As[cq0 + 0][r0] = pa0.x; As[cq0 + 1][r0] = pa0.y; As[cq0 + 2][r0] = pa0.z; As[cq0 + 3][r0] = pa0.w;
            As[cq1 + 0][r1] = pa1.x; As[cq1 + 1][r1] = pa1.y; As[cq1 + 2][r1] = pa1.z; As[cq1 + 3][r1] = pa1.w;
            Bs[cq0 + 0][r0] = pb0.x; Bs[cq0 + 1][r0] = pb0.y; Bs[cq0 + 2][r0] = pb0.z; Bs[cq0 + 3][r0] = pb0.w;
            Bs[cq1 + 0][r1] = pb1.x; Bs[cq1 + 1][r1] = pb1.y; Bs[cq1 + 2][r1] = pb1.z; Bs[cq1 + 3][r1] = pb1.w;
            __syncthreads();
        }
    }

#pragma unroll
    for (int i = 0; i < 4; i++) {
#pragma unroll
        for (int j = 0; j < 8; j++) {
            float lo, hi;
            upk2(lo, hi, acc2[i][j]);
            int n = n0 + tx * 8 + j;
            float bval = bias[n];
            int mA = m0 + ty * 8 + i * 2;
#pragma unroll
            for (int u = 0; u < 2; u++) {
                int m = mA + u;
                float v = (u == 0 ? lo : hi) + bval;
                if (SPLIT) {
                    int b = m / Tv, t = m % Tv;
                    int h = n / HDv, hd = n % HDv;
                    out[(((size_t)(b * Hv + h) * Tv) + t) * HDv + hd] = v;
                } else {
                    out[(size_t)m * Dv + n] = v;
                }
            }
        }
    }
}

// ---------------------------------------------------------------------------
// STP: per (b,h,t) row, compute q_stp[3] and cross(k3, v3)[3]. One warp/row.
// ---------------------------------------------------------------------------
__global__ __launch_bounds__(256) void stp_kernel(const float* __restrict__ Wqs,
                                                  const float* __restrict__ bqs,
                                                  const float* __restrict__ Wks,
                                                  const float* __restrict__ bks,
                                                  const float* __restrict__ Wvs,
                                                  const float* __restrict__ bvs) {
    int warp = (blockIdx.x * blockDim.x + threadIdx.x) >> 5;
    int lane = threadIdx.x & 31;
    if (warp >= Bv * Hv * Tv) return;

    const float* q = g_Q + (size_t)warp * HDv;
    const float* k = g_K + (size_t)warp * HDv;
    const float* v = g_V + (size_t)warp * HDv;

    float q0 = q[lane], q1 = q[lane + 32];
    float k0 = k[lane], k1 = k[lane + 32];
    float v0 = v[lane], v1 = v[lane + 32];

    float qs[3], k3[3], v3[3];
#pragma unroll
    for (int c = 0; c < 3; c++) {
        float pq = q0 * Wqs[c * HDv + lane] + q1 * Wqs[c * HDv + lane + 32];
        float pk = k0 * Wks[c * HDv + lane] + k1 * Wks[c * HDv + lane + 32];
        float pv = v0 * Wvs[c * HDv + lane] + v1 * Wvs[c * HDv + lane + 32];
#pragma unroll
        for (int o = 16; o > 0; o >>= 1) {
            pq += __shfl_xor_sync(0xffffffffu, pq, o);
            pk += __shfl_xor_sync(0xffffffffu, pk, o);
            pv += __shfl_xor_sync(0xffffffffu, pv, o);
        }
        qs[c] = pq + bqs[c];
        k3[c] = pk + bks[c];
        v3[c] = pv + bvs[c];
    }

    if (lane == 0) {
        g_QS[(size_t)warp * 3 + 0] = qs[0];
        g_QS[(size_t)warp * 3 + 1] = qs[1];
        g_QS[(size_t)warp * 3 + 2] = qs[2];
        g_CKV[(size_t)warp * 3 + 0] = k3[1] * v3[2] - k3[2] * v3[1];
        g_CKV[(size_t)warp * 3 + 1] = k3[2] * v3[0] - k3[0] * v3[2];
        g_CKV[(size_t)warp * 3 + 2] = k3[0] * v3[1] - k3[1] * v3[0];
    }
}

// ---------------------------------------------------------------------------
// Flash-style attention, f32x2 math. One thread per query row; K/V tiles of
// 32 keys staged in smem. 4 independent f32x2 accumulator chains for scores.
// ---------------------------------------------------------------------------
#define KT 32

__global__ __launch_bounds__(128) void attn_kernel(const float* __restrict__ temp_p) {
    const int b = blockIdx.z;
    const int h = blockIdx.y;
    const int qrow = blockIdx.x * 128 + threadIdx.x;
    const int tid = threadIdx.x;
    const float temp = *temp_p;

    const size_t head_off = ((size_t)(b * Hv + h)) * Tv * HDv;
    const float4* Kp4 = (const float4*)(g_K + head_off);
    const float4* Vp4 = (const float4*)(g_V + head_off);
    const ulonglong2* Qp = (const ulonglong2*)(g_Q + head_off + (size_t)qrow * HDv);
    const float* QSp = g_QS + ((size_t)(b * Hv + h)) * Tv * 3;
    const float* CKVp = g_CKV + ((size_t)(b * Hv + h)) * Tv * 3;

    u64 q2[32];
#pragma unroll
    for (int i = 0; i < 16; i++) {
        ulonglong2 qq = Qp[i];
        q2[2 * i] = qq.x;
        q2[2 * i + 1] = qq.y;
    }
    const float qs0 = QSp[qrow * 3 + 0];
    const float qs1 = QSp[qrow * 3 + 1];
    const float qs2 = QSp[qrow * 3 + 2];

    u64 acc2[32];
#pragma unroll
    for (int i = 0; i < 32; i++) acc2[i] = 0ull;
    float mval = -INFINITY;
    float lsum = 0.0f;

    __shared__ float4 Ks[KT][16];
    __shared__ float4 Vs[KT][16];
    __shared__ float Cs[KT][3];

    for (int kt = 0; kt < Tv; kt += KT) {
        // cooperative load: KT*16 float4 per tensor, 128 threads -> 4 each
#pragma unroll
        for (int it = 0; it < 4; it++) {
            int idx = tid + it * 128;     // 0..511
            int r = idx >> 4;
            int c = idx & 15;
            Ks[r][c] = Kp4[(size_t)(kt + r) * 16 + c];
            Vs[r][c] = Vp4[(size_t)(kt + r) * 16 + c];
        }
        if (tid < KT * 3) ((float*)Cs)[tid] = CKVp[kt * 3 + tid];
        __syncthreads();

        float sv[KT];
        float tmax = mval;
#pragma unroll
        for (int j = 0; j < KT; j++) {
            u64 su[4];
            su[0] = su[1] = su[2] = su[3] = 0ull;
            const ulonglong2* krow = (const ulonglong2*)&Ks[j][0];  // 16 entries
#pragma unroll
            for (int c8 = 0; c8 < 16; c8++) {
                ulonglong2 kk2 = krow[c8];
                su[(2 * c8) & 3] = fma2(q2[2 * c8], kk2.x, su[(2 * c8) & 3]);
                su[(2 * c8 + 1) & 3] = fma2(q2[2 * c8 + 1], kk2.y, su[(2 * c8 + 1) & 3]);
            }
            u64 sAB = add2(add2(su[0], su[1]), add2(su[2], su[3]));
            float slo, shi;
            upk2(slo, shi, sAB);
            float s = slo + shi;
            s += qs0 * Cs[j][0] + qs1 * Cs[j][1] + qs2 * Cs[j][2];
            s *= temp;
            sv[j] = s;
            tmax = fmaxf(tmax, s);
        }

        const float scale = __expf(mval - tmax);   // 0 on first tile (mval=-inf)
        mval = tmax;
        lsum *= scale;
        const u64 sp = pk2(scale, scale);
#pragma unroll
        for (int c = 0; c < 32; c++) acc2[c] = mul2(acc2[c], sp);

#pragma unroll
        for (int j = 0; j < KT; j++) {
            float p = __expf(sv[j] - mval);
            lsum += p;
            const u64 pp = pk2(p, p);
            const ulonglong2* vrow = (const ulonglong2*)&Vs[j][0];
#pragma unroll
            for (int c8 = 0; c8 < 16; c8++) {
                ulonglong2 vv2 = vrow[c8];
                acc2[2 * c8] = fma2(pp, vv2.x, acc2[2 * c8]);
                acc2[2 * c8 + 1] = fma2(pp, vv2.y, acc2[2 * c8 + 1]);
            }
        }
        __syncthreads();
    }

    const float inv = 1.0f / lsum;
    const u64 invp = pk2(inv, inv);
    ulonglong2* o = (ulonglong2*)(g_AO + ((size_t)(b * Tv + qrow)) * Dv + h * HDv);
#pragma unroll
    for (int c8 = 0; c8 < 16; c8++) {
        ulonglong2 ov;
        ov.x = mul2(acc2[2 * c8], invp);
        ov.y = mul2(acc2[2 * c8 + 1], invp);
        o[c8] = ov;
    }
}

// ---------------------------------------------------------------------------
extern "C" void kernel_launch(void* const* d_in, const int* in_sizes, int n_in,
                              void* d_out, int out_size) {
    const float* x   = (const float*)d_in[0];
    const float* Wq  = (const float*)d_in[1];
    const float* bq  = (const float*)d_in[2];
    const float* Wk  = (const float*)d_in[3];
    const float* bk  = (const float*)d_in[4];
    const float* Wv  = (const float*)d_in[5];
    const float* bv  = (const float*)d_in[6];
    const float* Wo  = (const float*)d_in[7];
    const float* bo  = (const float*)d_in[8];
    const float* Wqs = (const float*)d_in[9];
    const float* bqs = (const float*)d_in[10];
    const float* Wks = (const float*)d_in[11];
    const float* bks = (const float*)d_in[12];
    const float* Wvs = (const float*)d_in[13];
    const float* bvs = (const float*)d_in[14];
    const float* temp = (const float*)d_in[15];

    float *gQ, *gK, *gV, *gAO;
    cudaGetSymbolAddress((void**)&gQ, g_Q);
    cudaGetSymbolAddress((void**)&gK, g_K);
    cudaGetSymbolAddress((void**)&gV, g_V);
    cudaGetSymbolAddress((void**)&gAO, g_AO);

    dim3 ggrid(Dv / 128, Mv / 128);   // (8, 32)
    gemm_proj<true><<<ggrid, 256>>>(x, Wq, bq, gQ);
    gemm_proj<true><<<ggrid, 256>>>(x, Wk, bk, gK);
    gemm_proj<true><<<ggrid, 256>>>(x, Wv, bv, gV);

    int nwarps = Bv * Hv * Tv;                 // 65536
    stp_kernel<<<nwarps / 8, 256>>>(Wqs, bqs, Wks, bks, Wvs, bvs);

    dim3 agrid(Tv / 128, Hv, Bv);              // (16, 16, 2)
    attn_kernel<<<agrid, 128>>>(temp);

    gemm_proj<false><<<ggrid, 256>>>(gAO, Wo, bo, (float*)d_out);
}

// round 6
// speedup vs baseline: 1.8667x; 1.8667x over previous
#include <cuda_runtime.h>
#include <math.h>
#include <stdint.h>

#define Bv 2
#define Tv 2048
#define Dv 1024
#define Hv 16
#define HDv 64
#define Mv (Bv * Tv)   // 4096

// Scratch (allocation-free rule: __device__ globals)
__device__ float g_Q[Bv * Hv * Tv * HDv];   // [b,h,t,hd]
__device__ float g_K[Bv * Hv * Tv * HDv];
__device__ float g_V[Bv * Hv * Tv * HDv];
__device__ float g_AO[Bv * Tv * Dv];        // attention out, [b,t,h*HD+hd]
__device__ float g_QS[Bv * Hv * Tv * 3];
__device__ float g_CKV[Bv * Hv * Tv * 3];

// ======================= base-ISA helpers (sm_80-class) =====================
__device__ __forceinline__ uint32_t smem_u32(const void* p) {
    uint32_t a;
    asm("{ .reg .u64 t; cvta.to.shared.u64 t, %1; cvt.u32.u64 %0, t; }" : "=r"(a) : "l"(p));
    return a;
}
__device__ __forceinline__ void cp16(uint32_t dst, const void* src) {
    asm volatile("cp.async.cg.shared.global [%0], [%1], 16;" :: "r"(dst), "l"(src) : "memory");
}
__device__ __forceinline__ void cp_commit() {
    asm volatile("cp.async.commit_group;" ::: "memory");
}
template <int N>
__device__ __forceinline__ void cp_wait() {
    asm volatile("cp.async.wait_group %0;" :: "n"(N) : "memory");
}
__device__ __forceinline__ void ldsm4(uint32_t& r0, uint32_t& r1, uint32_t& r2, uint32_t& r3,
                                      uint32_t addr) {
    asm volatile("ldmatrix.sync.aligned.m8n8.x4.shared.b16 {%0,%1,%2,%3}, [%4];"
                 : "=r"(r0), "=r"(r1), "=r"(r2), "=r"(r3) : "r"(addr));
}
__device__ __forceinline__ void ldsm2(uint32_t& r0, uint32_t& r1, uint32_t addr) {
    asm volatile("ldmatrix.sync.aligned.m8n8.x2.shared.b16 {%0,%1}, [%2];"
                 : "=r"(r0), "=r"(r1) : "r"(addr));
}
__device__ __forceinline__ void mma_tf32(float* d, uint32_t a0, uint32_t a1, uint32_t a2,
                                         uint32_t a3, uint32_t b0, uint32_t b1) {
    asm volatile(
        "mma.sync.aligned.m16n8k8.row.col.f32.tf32.tf32.f32 "
        "{%0,%1,%2,%3}, {%4,%5,%6,%7}, {%8,%9}, {%0,%1,%2,%3};"
        : "+f"(d[0]), "+f"(d[1]), "+f"(d[2]), "+f"(d[3])
        : "r"(a0), "r"(a1), "r"(a2), "r"(a3), "r"(b0), "r"(b1));
}
// 3xTF32 split: hi = tf32(x), lo = tf32(x - hi)
__device__ __forceinline__ void split_tf32(uint32_t raw, uint32_t& hi, uint32_t& lo) {
    float f = __uint_as_float(raw);
    asm("cvt.rna.tf32.f32 %0, %1;" : "=r"(hi) : "f"(f));
    float r = f - __uint_as_float(hi);
    asm("cvt.rna.tf32.f32 %0, %1;" : "=r"(lo) : "f"(r));
}

// ---------------------------------------------------------------------------
// 3xTF32 mma.sync GEMM: C[m,n] = sum_k X[m,k] * W[n,k] + bias[n]
// M=4096, N=1024, K=1024. Tile 128x128 per CTA (8 warps, 2x4), K-chunks of 32,
// cp.async double-buffered smem (pitch 36 floats -> conflict-free ldmatrix).
// Error-compensated tf32: D += Ah*Bh + Ah*Bl + Al*Bh (fp32-class accuracy).
// ---------------------------------------------------------------------------
#define PITCH 36                     // floats per smem row
#define PITCHB (PITCH * 4)           // 144 bytes
#define STAGE_BYTES (128 * PITCHB)   // 18432 per matrix per stage
#define KCH 32
#define NSTEP (1024 / KCH)           // 32

template <bool SPLIT>
__global__ __launch_bounds__(256) void gemm_mma(const float* __restrict__ X,
                                                const float* __restrict__ W,
                                                const float* __restrict__ bias,
                                                float* __restrict__ out) {
    extern __shared__ char dsm[];
    const uint32_t sbase = smem_u32(dsm);
    const int K = 1024;
    const int n0 = blockIdx.x * 128;
    const int m0 = blockIdx.y * 128;
    const int tid = threadIdx.x;
    const int lane = tid & 31;
    const int wid = tid >> 5;
    const int wm = wid >> 2;   // 0..1  (64 rows each)
    const int wn = wid & 3;    // 0..3  (32 cols each)

    uint32_t Ab[2], Wb[2];
    Ab[0] = sbase;                     Wb[0] = sbase + STAGE_BYTES;
    Ab[1] = sbase + 2 * STAGE_BYTES;   Wb[1] = sbase + 3 * STAGE_BYTES;

    const uint32_t offA = ((lane & 7) + ((lane >> 3) & 1) * 8) * PITCHB + ((lane >> 4) & 1) * 16;
    const uint32_t offB = (lane & 7) * PITCHB + ((lane >> 3) & 1) * 16;
    const uint32_t aWarp = (uint32_t)(wm * 64) * PITCHB + offA;
    const uint32_t bWarp = (uint32_t)(wn * 32) * PITCHB + offB;

    const int lrow0 = tid >> 3;        // 0..31, +32 per it
    const int lc4 = (tid & 7) * 16;    // byte col

    float acc[4][4][4];
#pragma unroll
    for (int i = 0; i < 4; i++)
#pragma unroll
        for (int j = 0; j < 4; j++)
#pragma unroll
            for (int r = 0; r < 4; r++) acc[i][j][r] = 0.0f;

    // prologue: stages 0 and 1
#pragma unroll
    for (int s = 0; s < 2; s++) {
        const int k0 = s * KCH;
#pragma unroll
        for (int it = 0; it < 4; it++) {
            int row = lrow0 + it * 32;
            cp16(Ab[s] + (uint32_t)row * PITCHB + lc4, &X[(size_t)(m0 + row) * K + k0] + (lc4 >> 2));
            cp16(Wb[s] + (uint32_t)row * PITCHB + lc4, &W[(size_t)(n0 + row) * K + k0] + (lc4 >> 2));
        }
        cp_commit();
    }

    for (int c = 0; c < NSTEP; c++) {
        cp_wait<1>();
        __syncthreads();
        const int s = c & 1;
        const uint32_t Abase = Ab[s] + aWarp;
        const uint32_t Bbase = Wb[s] + bWarp;

#pragma unroll
        for (int ka = 0; ka < 4; ka++) {       // 4 k8-atoms per chunk
            uint32_t bh0[4], bh1[4], bl0[4], bl1[4];
#pragma unroll
            for (int jn = 0; jn < 4; jn++) {
                uint32_t r0, r1;
                ldsm2(r0, r1, Bbase + (uint32_t)(jn * 8) * PITCHB + ka * 32);
                split_tf32(r0, bh0[jn], bl0[jn]);
                split_tf32(r1, bh1[jn], bl1[jn]);
            }
#pragma unroll
            for (int i = 0; i < 4; i++) {
                uint32_t r0, r1, r2, r3;
                ldsm4(r0, r1, r2, r3, Abase + (uint32_t)(i * 16) * PITCHB + ka * 32);
                uint32_t ah[4], al[4];
                split_tf32(r0, ah[0], al[0]);
                split_tf32(r1, ah[1], al[1]);
                split_tf32(r2, ah[2], al[2]);
                split_tf32(r3, ah[3], al[3]);
#pragma unroll
                for (int jn = 0; jn < 4; jn++) {
                    mma_tf32(acc[i][jn], ah[0], ah[1], ah[2], ah[3], bh0[jn], bh1[jn]);
                    mma_tf32(acc[i][jn], ah[0], ah[1], ah[2], ah[3], bl0[jn], bl1[jn]);
                    mma_tf32(acc[i][jn], al[0], al[1], al[2], al[3], bh0[jn], bh1[jn]);
                }
            }
        }
        __syncthreads();   // all warps done reading stage s before refill

        const int nxt = c + 2;
        if (nxt < NSTEP) {
            const int k0 = nxt * KCH;
#pragma unroll
            for (int it = 0; it < 4; it++) {
                int row = lrow0 + it * 32;
                cp16(Ab[s] + (uint32_t)row * PITCHB + lc4, &X[(size_t)(m0 + row) * K + k0] + (lc4 >> 2));
                cp16(Wb[s] + (uint32_t)row * PITCHB + lc4, &W[(size_t)(n0 + row) * K + k0] + (lc4 >> 2));
            }
        }
        cp_commit();
    }

    // epilogue: bias + scatter
#pragma unroll
    for (int i = 0; i < 4; i++) {
        const int mlo = m0 + wm * 64 + i * 16 + (lane >> 2);
#pragma unroll
        for (int jn = 0; jn < 4; jn++) {
            const int nb = n0 + wn * 32 + jn * 8 + (lane & 3) * 2;
            const float2 bb = *(const float2*)&bias[nb];
            float2 v0 = make_float2(acc[i][jn][0] + bb.x, acc[i][jn][1] + bb.y);
            float2 v1 = make_float2(acc[i][jn][2] + bb.x, acc[i][jn][3] + bb.y);
#pragma unroll
            for (int u = 0; u < 2; u++) {
                const int m = mlo + u * 8;
                const float2 v = (u == 0) ? v0 : v1;
                if (SPLIT) {
                    int b = m >> 11, t = m & 2047;
                    int h = nb >> 6, hd = nb & 63;
                    *(float2*)&out[(((size_t)(b * Hv + h) * Tv) + t) * HDv + hd] = v;
                } else {
                    *(float2*)&out[(size_t)m * Dv + nb] = v;
                }
            }
        }
    }
}

// ---------------------------------------------------------------------------
// STP: per (b,h,t) row, compute q_stp[3] and cross(k3, v3)[3]. One warp/row.
// ---------------------------------------------------------------------------
__global__ __launch_bounds__(256) void stp_kernel(const float* __restrict__ Wqs,
                                                  const float* __restrict__ bqs,
                                                  const float* __restrict__ Wks,
                                                  const float* __restrict__ bks,
                                                  const float* __restrict__ Wvs,
                                                  const float* __restrict__ bvs) {
    int warp = (blockIdx.x * blockDim.x + threadIdx.x) >> 5;
    int lane = threadIdx.x & 31;
    if (warp >= Bv * Hv * Tv) return;

    const float* q = g_Q + (size_t)warp * HDv;
    const float* k = g_K + (size_t)warp * HDv;
    const float* v = g_V + (size_t)warp * HDv;

    float q0 = q[lane], q1 = q[lane + 32];
    float k0 = k[lane], k1 = k[lane + 32];
    float v0 = v[lane], v1 = v[lane + 32];

    float qs[3], k3[3], v3[3];
#pragma unroll
    for (int c = 0; c < 3; c++) {
        float pq = q0 * Wqs[c * HDv + lane] + q1 * Wqs[c * HDv + lane + 32];
        float pk = k0 * Wks[c * HDv + lane] + k1 * Wks[c * HDv + lane + 32];
        float pv = v0 * Wvs[c * HDv + lane] + v1 * Wvs[c * HDv + lane + 32];
#pragma unroll
        for (int o = 16; o > 0; o >>= 1) {
            pq += __shfl_xor_sync(0xffffffffu, pq, o);
            pk += __shfl_xor_sync(0xffffffffu, pk, o);
            pv += __shfl_xor_sync(0xffffffffu, pv, o);
        }
        qs[c] = pq + bqs[c];
        k3[c] = pk + bks[c];
        v3[c] = pv + bvs[c];
    }

    if (lane == 0) {
        g_QS[(size_t)warp * 3 + 0] = qs[0];
        g_QS[(size_t)warp * 3 + 1] = qs[1];
        g_QS[(size_t)warp * 3 + 2] = qs[2];
        g_CKV[(size_t)warp * 3 + 0] = k3[1] * v3[2] - k3[2] * v3[1];
        g_CKV[(size_t)warp * 3 + 1] = k3[2] * v3[0] - k3[0] * v3[2];
        g_CKV[(size_t)warp * 3 + 2] = k3[0] * v3[1] - k3[1] * v3[0];
    }
}

// ---------------------------------------------------------------------------
// Flash-style attention (round-2 scalar form, known good).
// ---------------------------------------------------------------------------
#define KT 32

__global__ __launch_bounds__(128) void attn_kernel(const float* __restrict__ temp_p) {
    const int b = blockIdx.z;
    const int h = blockIdx.y;
    const int qrow = blockIdx.x * 128 + threadIdx.x;
    const int tid = threadIdx.x;
    const float temp = *temp_p;

    const size_t head_off = ((size_t)(b * Hv + h)) * Tv * HDv;
    const float4* Kp4 = (const float4*)(g_K + head_off);
    const float4* Vp4 = (const float4*)(g_V + head_off);
    const float4* Qp4 = (const float4*)(g_Q + head_off + (size_t)qrow * HDv);
    const float* QSp = g_QS + ((size_t)(b * Hv + h)) * Tv * 3;
    const float* CKVp = g_CKV + ((size_t)(b * Hv + h)) * Tv * 3;

    float4 q[16];
#pragma unroll
    for (int i = 0; i < 16; i++) q[i] = Qp4[i];
    const float qs0 = QSp[qrow * 3 + 0];
    const float qs1 = QSp[qrow * 3 + 1];
    const float qs2 = QSp[qrow * 3 + 2];

    float4 acc[16];
#pragma unroll
    for (int i = 0; i < 16; i++) acc[i] = make_float4(0.f, 0.f, 0.f, 0.f);
    float mval = -INFINITY;
    float lsum = 0.0f;

    __shared__ float4 Ks[KT][16];
    __shared__ float4 Vs[KT][16];
    __shared__ float Cs[KT][3];

    for (int kt = 0; kt < Tv; kt += KT) {
#pragma unroll
        for (int it = 0; it < 4; it++) {
            int idx = tid + it * 128;
            int r = idx >> 4;
            int c = idx & 15;
            Ks[r][c] = Kp4[(size_t)(kt + r) * 16 + c];
            Vs[r][c] = Vp4[(size_t)(kt + r) * 16 + c];
        }
        if (tid < KT * 3) ((float*)Cs)[tid] = CKVp[kt * 3 + tid];
        __syncthreads();

        float sv[KT];
        float tmax = mval;
#pragma unroll
        for (int j = 0; j < KT; j++) {
            float s = 0.0f;
#pragma unroll
            for (int c = 0; c < 16; c++) {
                float4 kk = Ks[j][c];
                s += q[c].x * kk.x + q[c].y * kk.y + q[c].z * kk.z + q[c].w * kk.w;
            }
            s += qs0 * Cs[j][0] + qs1 * Cs[j][1] + qs2 * Cs[j][2];
            s *= temp;
            sv[j] = s;
            tmax = fmaxf(tmax, s);
        }

        const float scale = __expf(mval - tmax);
        mval = tmax;
        lsum *= scale;
#pragma unroll
        for (int c = 0; c < 16; c++) {
            acc[c].x *= scale; acc[c].y *= scale; acc[c].z *= scale; acc[c].w *= scale;
        }
#pragma unroll
        for (int j = 0; j < KT; j++) {
            float p = __expf(sv[j] - mval);
            lsum += p;
#pragma unroll
            for (int c = 0; c < 16; c++) {
                float4 vv = Vs[j][c];
                acc[c].x += p * vv.x;
                acc[c].y += p * vv.y;
                acc[c].z += p * vv.z;
                acc[c].w += p * vv.w;
            }
        }
        __syncthreads();
    }

    const float inv = 1.0f / lsum;
    float4* o = (float4*)(g_AO + ((size_t)(b * Tv + qrow)) * Dv + h * HDv);
#pragma unroll
    for (int c = 0; c < 16; c++)
        o[c] = make_float4(acc[c].x * inv, acc[c].y * inv, acc[c].z * inv, acc[c].w * inv);
}

// ---------------------------------------------------------------------------
extern "C" void kernel_launch(void* const* d_in, const int* in_sizes, int n_in,
                              void* d_out, int out_size) {
    const float* x   = (const float*)d_in[0];
    const float* Wq  = (const float*)d_in[1];
    const float* bq  = (const float*)d_in[2];
    const float* Wk  = (const float*)d_in[3];
    const float* bk  = (const float*)d_in[4];
    const float* Wv  = (const float*)d_in[5];
    const float* bv  = (const float*)d_in[6];
    const float* Wo  = (const float*)d_in[7];
    const float* bo  = (const float*)d_in[8];
    const float* Wqs = (const float*)d_in[9];
    const float* bqs = (const float*)d_in[10];
    const float* Wks = (const float*)d_in[11];
    const float* bks = (const float*)d_in[12];
    const float* Wvs = (const float*)d_in[13];
    const float* bvs = (const float*)d_in[14];
    const float* temp = (const float*)d_in[15];

    float *gQ, *gK, *gV, *gAO;
    cudaGetSymbolAddress((void**)&gQ, g_Q);
    cudaGetSymbolAddress((void**)&gK, g_K);
    cudaGetSymbolAddress((void**)&gV, g_V);
    cudaGetSymbolAddress((void**)&gAO, g_AO);

    const int dyn_smem = 4 * STAGE_BYTES;   // 73728
    cudaFuncSetAttribute(gemm_mma<true>, cudaFuncAttributeMaxDynamicSharedMemorySize, dyn_smem);
    cudaFuncSetAttribute(gemm_mma<false>, cudaFuncAttributeMaxDynamicSharedMemorySize, dyn_smem);

    dim3 ggrid(Dv / 128, Mv / 128);   // (8, 32)
    gemm_mma<true><<<ggrid, 256, dyn_smem>>>(x, Wq, bq, gQ);
    gemm_mma<true><<<ggrid, 256, dyn_smem>>>(x, Wk, bk, gK);
    gemm_mma<true><<<ggrid, 256, dyn_smem>>>(x, Wv, bv, gV);

    int nwarps = Bv * Hv * Tv;                 // 65536
    stp_kernel<<<nwarps / 8, 256>>>(Wqs, bqs, Wks, bks, Wvs, bvs);

    dim3 agrid(Tv / 128, Hv, Bv);              // (16, 16, 2)
    attn_kernel<<<agrid, 128>>>(temp);

    gemm_mma<false><<<ggrid, 256, dyn_smem>>>(gAO, Wo, bo, (float*)d_out);
}

// round 7
// speedup vs baseline: 2.5032x; 1.3410x over previous
#include <cuda_runtime.h>
#include <math.h>
#include <stdint.h>

#define Bv 2
#define Tv 2048
#define Dv 1024
#define Hv 16
#define HDv 64
#define Mv (Bv * Tv)   // 4096

// Scratch (allocation-free rule: __device__ globals)
__device__ float g_Qe[Bv * Hv * Tv * 80];   // [b,h,t,80]: 0-63 q, 64-66 qs, 67-71 zero
__device__ float g_Ke[Bv * Hv * Tv * 80];   // [b,h,t,80]: 0-63 k, 64-66 ckv, 67-71 zero
__device__ float g_V [Bv * Hv * Tv * HDv];  // [b,h,t,hd]
__device__ float g_Vt[Bv * Hv * HDv * Tv];  // [b,h,hd,t] (transposed for PV mma)
__device__ float g_AO[Bv * Tv * Dv];        // attention out, [b,t,h*HD+hd]

// ======================= base-ISA helpers (sm_80-class) =====================
__device__ __forceinline__ uint32_t smem_u32(const void* p) {
    uint32_t a;
    asm("{ .reg .u64 t; cvta.to.shared.u64 t, %1; cvt.u32.u64 %0, t; }" : "=r"(a) : "l"(p));
    return a;
}
__device__ __forceinline__ void cp16(uint32_t dst, const void* src) {
    asm volatile("cp.async.cg.shared.global [%0], [%1], 16;" :: "r"(dst), "l"(src) : "memory");
}
__device__ __forceinline__ void cp_commit() {
    asm volatile("cp.async.commit_group;" ::: "memory");
}
template <int N>
__device__ __forceinline__ void cp_wait() {
    asm volatile("cp.async.wait_group %0;" :: "n"(N) : "memory");
}
__device__ __forceinline__ void ldsm4(uint32_t& r0, uint32_t& r1, uint32_t& r2, uint32_t& r3,
                                      uint32_t addr) {
    asm volatile("ldmatrix.sync.aligned.m8n8.x4.shared.b16 {%0,%1,%2,%3}, [%4];"
                 : "=r"(r0), "=r"(r1), "=r"(r2), "=r"(r3) : "r"(addr));
}
__device__ __forceinline__ void ldsm2(uint32_t& r0, uint32_t& r1, uint32_t addr) {
    asm volatile("ldmatrix.sync.aligned.m8n8.x2.shared.b16 {%0,%1}, [%2];"
                 : "=r"(r0), "=r"(r1) : "r"(addr));
}
__device__ __forceinline__ void sts64(uint32_t addr, float x, float y) {
    asm volatile("st.shared.v2.f32 [%0], {%1,%2};" :: "r"(addr), "f"(x), "f"(y) : "memory");
}
__device__ __forceinline__ void mma_tf32(float* d, const uint32_t* a, uint32_t b0, uint32_t b1) {
    asm volatile(
        "mma.sync.aligned.m16n8k8.row.col.f32.tf32.tf32.f32 "
        "{%0,%1,%2,%3}, {%4,%5,%6,%7}, {%8,%9}, {%0,%1,%2,%3};"
        : "+f"(d[0]), "+f"(d[1]), "+f"(d[2]), "+f"(d[3])
        : "r"(a[0]), "r"(a[1]), "r"(a[2]), "r"(a[3]), "r"(b0), "r"(b1));
}
__device__ __forceinline__ void mma_tf32r(float* d, uint32_t a0, uint32_t a1, uint32_t a2,
                                          uint32_t a3, uint32_t b0, uint32_t b1) {
    asm volatile(
        "mma.sync.aligned.m16n8k8.row.col.f32.tf32.tf32.f32 "
        "{%0,%1,%2,%3}, {%4,%5,%6,%7}, {%8,%9}, {%0,%1,%2,%3};"
        : "+f"(d[0]), "+f"(d[1]), "+f"(d[2]), "+f"(d[3])
        : "r"(a0), "r"(a1), "r"(a2), "r"(a3), "r"(b0), "r"(b1));
}
// 3xTF32 split: hi = tf32(x), lo = tf32(x - hi)
__device__ __forceinline__ void split_tf32(uint32_t raw, uint32_t& hi, uint32_t& lo) {
    float f = __uint_as_float(raw);
    asm("cvt.rna.tf32.f32 %0, %1;" : "=r"(hi) : "f"(f));
    float r = f - __uint_as_float(hi);
    asm("cvt.rna.tf32.f32 %0, %1;" : "=r"(lo) : "f"(r));
}

// ---------------------------------------------------------------------------
// 3xTF32 mma.sync GEMM: C[m,n] = sum_k X[m,k] * W[n,k] + bias[n]
// MODE 0: plain row-major out. MODE 1: head-split extended pitch-80 (Q/K).
// MODE 2: V dual-write (transposed g_Vt to out, head-split to out2).
// ---------------------------------------------------------------------------
#define PITCH 36
#define PITCHB (PITCH * 4)           // 144 bytes
#define STAGE_BYTES (128 * PITCHB)   // 18432
#define KCH 32
#define NSTEP (1024 / KCH)           // 32

template <int MODE>
__global__ __launch_bounds__(256) void gemm_mma(const float* __restrict__ X,
                                                const float* __restrict__ W,
                                                const float* __restrict__ bias,
                                                float* __restrict__ out,
                                                float* __restrict__ out2) {
    extern __shared__ char dsm[];
    const uint32_t sbase = smem_u32(dsm);
    const int K = 1024;
    const int n0 = blockIdx.x * 128;
    const int m0 = blockIdx.y * 128;
    const int tid = threadIdx.x;
    const int lane = tid & 31;
    const int wid = tid >> 5;
    const int wm = wid >> 2;
    const int wn = wid & 3;

    uint32_t Ab[2], Wb[2];
    Ab[0] = sbase;                     Wb[0] = sbase + STAGE_BYTES;
    Ab[1] = sbase + 2 * STAGE_BYTES;   Wb[1] = sbase + 3 * STAGE_BYTES;

    const uint32_t offA = ((lane & 7) + ((lane >> 3) & 1) * 8) * PITCHB + ((lane >> 4) & 1) * 16;
    const uint32_t offB = (lane & 7) * PITCHB + ((lane >> 3) & 1) * 16;
    const uint32_t aWarp = (uint32_t)(wm * 64) * PITCHB + offA;
    const uint32_t bWarp = (uint32_t)(wn * 32) * PITCHB + offB;

    const int lrow0 = tid >> 3;
    const int lc4 = (tid & 7) * 16;

    float acc[4][4][4];
#pragma unroll
    for (int i = 0; i < 4; i++)
#pragma unroll
        for (int j = 0; j < 4; j++)
#pragma unroll
            for (int r = 0; r < 4; r++) acc[i][j][r] = 0.0f;

#pragma unroll
    for (int s = 0; s < 2; s++) {
        const int k0 = s * KCH;
#pragma unroll
        for (int it = 0; it < 4; it++) {
            int row = lrow0 + it * 32;
            cp16(Ab[s] + (uint32_t)row * PITCHB + lc4, &X[(size_t)(m0 + row) * K + k0] + (lc4 >> 2));
            cp16(Wb[s] + (uint32_t)row * PITCHB + lc4, &W[(size_t)(n0 + row) * K + k0] + (lc4 >> 2));
        }
        cp_commit();
    }

    for (int c = 0; c < NSTEP; c++) {
        cp_wait<1>();
        __syncthreads();
        const int s = c & 1;
        const uint32_t Abase = Ab[s] + aWarp;
        const uint32_t Bbase = Wb[s] + bWarp;

#pragma unroll
        for (int ka = 0; ka < 4; ka++) {
            uint32_t bh0[4], bh1[4], bl0[4], bl1[4];
#pragma unroll
            for (int jn = 0; jn < 4; jn++) {
                uint32_t r0, r1;
                ldsm2(r0, r1, Bbase + (uint32_t)(jn * 8) * PITCHB + ka * 32);
                split_tf32(r0, bh0[jn], bl0[jn]);
                split_tf32(r1, bh1[jn], bl1[jn]);
            }
#pragma unroll
            for (int i = 0; i < 4; i++) {
                uint32_t r0, r1, r2, r3;
                ldsm4(r0, r1, r2, r3, Abase + (uint32_t)(i * 16) * PITCHB + ka * 32);
                uint32_t ah[4], al[4];
                split_tf32(r0, ah[0], al[0]);
                split_tf32(r1, ah[1], al[1]);
                split_tf32(r2, ah[2], al[2]);
                split_tf32(r3, ah[3], al[3]);
#pragma unroll
                for (int jn = 0; jn < 4; jn++) {
                    mma_tf32(acc[i][jn], ah, bh0[jn], bh1[jn]);
                    mma_tf32(acc[i][jn], ah, bl0[jn], bl1[jn]);
                    mma_tf32(acc[i][jn], al, bh0[jn], bh1[jn]);
                }
            }
        }
        __syncthreads();

        const int nxt = c + 2;
        if (nxt < NSTEP) {
            const int k0 = nxt * KCH;
#pragma unroll
            for (int it = 0; it < 4; it++) {
                int row = lrow0 + it * 32;
                cp16(Ab[s] + (uint32_t)row * PITCHB + lc4, &X[(size_t)(m0 + row) * K + k0] + (lc4 >> 2));
                cp16(Wb[s] + (uint32_t)row * PITCHB + lc4, &W[(size_t)(n0 + row) * K + k0] + (lc4 >> 2));
            }
        }
        cp_commit();
    }

#pragma unroll
    for (int i = 0; i < 4; i++) {
        const int mlo = m0 + wm * 64 + i * 16 + (lane >> 2);
#pragma unroll
        for (int jn = 0; jn < 4; jn++) {
            const int nb = n0 + wn * 32 + jn * 8 + (lane & 3) * 2;
            const float2 bb = *(const float2*)&bias[nb];
            float2 v0 = make_float2(acc[i][jn][0] + bb.x, acc[i][jn][1] + bb.y);
            float2 v1 = make_float2(acc[i][jn][2] + bb.x, acc[i][jn][3] + bb.y);
#pragma unroll
            for (int u = 0; u < 2; u++) {
                const int m = mlo + u * 8;
                const float2 v = (u == 0) ? v0 : v1;
                if (MODE == 0) {
                    *(float2*)&out[(size_t)m * Dv + nb] = v;
                } else if (MODE == 1) {
                    int b = m >> 11, t = m & 2047;
                    int h = nb >> 6, hd = nb & 63;
                    *(float2*)&out[((size_t)(b * Hv + h) * Tv + t) * 80 + hd] = v;
                } else {
                    int b = m >> 11, t = m & 2047;
                    int h = nb >> 6, hd = nb & 63;
                    size_t vt = ((size_t)((b * Hv + h) * HDv + hd)) * Tv + t;
                    out[vt] = v.x;
                    out[vt + Tv] = v.y;
                    *(float2*)&out2[(((size_t)(b * Hv + h) * Tv) + t) * HDv + hd] = v;
                }
            }
        }
    }
}

// ---------------------------------------------------------------------------
// STP: per (b,h,t) row, compute q_stp[3] and cross(k3, v3)[3]; write into the
// extended cols (64..71) of g_Qe / g_Ke. One warp/row.
// ---------------------------------------------------------------------------
__global__ __launch_bounds__(256) void stp_kernel(const float* __restrict__ Wqs,
                                                  const float* __restrict__ bqs,
                                                  const float* __restrict__ Wks,
                                                  const float* __restrict__ bks,
                                                  const float* __restrict__ Wvs,
                                                  const float* __restrict__ bvs) {
    int warp = (blockIdx.x * blockDim.x + threadIdx.x) >> 5;
    int lane = threadIdx.x & 31;
    if (warp >= Bv * Hv * Tv) return;

    const float* q = g_Qe + (size_t)warp * 80;
    const float* k = g_Ke + (size_t)warp * 80;
    const float* v = g_V + (size_t)warp * HDv;

    float q0 = q[lane], q1 = q[lane + 32];
    float k0 = k[lane], k1 = k[lane + 32];
    float v0 = v[lane], v1 = v[lane + 32];

    float qs[3], k3[3], v3[3];
#pragma unroll
    for (int c = 0; c < 3; c++) {
        float pq = q0 * Wqs[c * HDv + lane] + q1 * Wqs[c * HDv + lane + 32];
        float pk = k0 * Wks[c * HDv + lane] + k1 * Wks[c * HDv + lane + 32];
        float pv = v0 * Wvs[c * HDv + lane] + v1 * Wvs[c * HDv + lane + 32];
#pragma unroll
        for (int o = 16; o > 0; o >>= 1) {
            pq += __shfl_xor_sync(0xffffffffu, pq, o);
            pk += __shfl_xor_sync(0xffffffffu, pk, o);
            pv += __shfl_xor_sync(0xffffffffu, pv, o);
        }
        qs[c] = pq + bqs[c];
        k3[c] = pk + bks[c];
        v3[c] = pv + bvs[c];
    }

    if (lane == 0) {
        float4* qe = (float4*)(g_Qe + (size_t)warp * 80 + 64);
        qe[0] = make_float4(qs[0], qs[1], qs[2], 0.f);
        qe[1] = make_float4(0.f, 0.f, 0.f, 0.f);
        float c0 = k3[1] * v3[2] - k3[2] * v3[1];
        float c1 = k3[2] * v3[0] - k3[0] * v3[2];
        float c2 = k3[0] * v3[1] - k3[1] * v3[0];
        float4* ke = (float4*)(g_Ke + (size_t)warp * 80 + 64);
        ke[0] = make_float4(c0, c1, c2, 0.f);
        ke[1] = make_float4(0.f, 0.f, 0.f, 0.f);
    }
}

// ---------------------------------------------------------------------------
// mma.sync flash attention. CTA = 128 q-rows of one head; 8 warps x 16 rows.
// S = Qe(72) . Ke(72)^T via 3xTF32; online softmax; O += P.V via 3xTF32
// (P through per-warp smem; V pre-transposed in g_Vt).
// Smem: K stages [0, 43008), V stages [43008, 77824), P [77824, 112640).
// ---------------------------------------------------------------------------
#define QPB 336   // Q/K smem pitch bytes (84 floats; 336 % 128 = 80 -> conflict-free)
#define VPB 272   // V/P smem pitch bytes (68 floats; 272 % 128 = 16 -> conflict-free)
#define ATT_SMEM 112640

__global__ __launch_bounds__(256, 1) void attn_mma(const float* __restrict__ temp_p) {
    extern __shared__ char dsm[];
    const uint32_t base = smem_u32(dsm);
    const int b = blockIdx.z, h = blockIdx.y;
    const int q0 = blockIdx.x * 128;
    const int tid = threadIdx.x, lane = tid & 31, wid = tid >> 5;
    const float temp = *temp_p;

    const float* Qe = g_Qe + ((size_t)(b * Hv + h) * Tv + q0) * 80;
    const float* Ke = g_Ke + (size_t)(b * Hv + h) * Tv * 80;
    const float* Vt = g_Vt + (size_t)(b * Hv + h) * HDv * Tv;

    // ---- stage Q (borrow K region), split to registers ----
#pragma unroll
    for (int i = 0; i < 10; i++) {
        int idx = tid + i * 256;
        int row = idx / 20, c = idx % 20;
        cp16(base + (uint32_t)row * QPB + c * 16, Qe + row * 80 + c * 4);
    }
    cp_commit();
    cp_wait<0>();
    __syncthreads();

    uint32_t qh[9][4], ql[9][4];
    {
        const uint32_t qa = base + (uint32_t)(wid * 16) * QPB +
            ((lane & 7) + ((lane >> 3) & 1) * 8) * QPB + ((lane >> 4) & 1) * 16;
#pragma unroll
        for (int ka = 0; ka < 9; ka++) {
            uint32_t r0, r1, r2, r3;
            ldsm4(r0, r1, r2, r3, qa + ka * 32);
            split_tf32(r0, qh[ka][0], ql[ka][0]);
            split_tf32(r1, qh[ka][1], ql[ka][1]);
            split_tf32(r2, qh[ka][2], ql[ka][2]);
            split_tf32(r3, qh[ka][3], ql[ka][3]);
        }
    }
    __syncthreads();   // Q staging area free before K loads

    float of[8][4];
#pragma unroll
    for (int j = 0; j < 8; j++)
#pragma unroll
        for (int r = 0; r < 4; r++) of[j][r] = 0.0f;
    float m0 = -INFINITY, m1 = -INFINITY, l0 = 0.f, l1 = 0.f;

    auto load_tile = [&](int kt, int s) {
        uint32_t kb = base + (uint32_t)s * 21504u;
#pragma unroll
        for (int i = 0; i < 5; i++) {
            int idx = tid + i * 256;
            int row = idx / 20, c = idx % 20;
            cp16(kb + (uint32_t)row * QPB + c * 16, Ke + (size_t)(kt * 64 + row) * 80 + c * 4);
        }
        uint32_t vb = base + 43008u + (uint32_t)s * 17408u;
#pragma unroll
        for (int i = 0; i < 4; i++) {
            int idx = tid + i * 256;
            int row = idx >> 4, c = idx & 15;
            cp16(vb + (uint32_t)row * VPB + c * 16, Vt + (size_t)row * Tv + kt * 64 + c * 4);
        }
        cp_commit();
    };

    load_tile(0, 0);
    load_tile(1, 1);

    const uint32_t pw = base + 77824u + (uint32_t)wid * 4352u;
    const uint32_t offAP = ((lane & 7) + ((lane >> 3) & 1) * 8) * VPB + ((lane >> 4) & 1) * 16;
    const int rquad = lane >> 2, qq = lane & 3;

    for (int kt = 0; kt < 32; kt++) {
        cp_wait<1>();
        __syncthreads();
        const int s = kt & 1;
        const uint32_t kb = base + (uint32_t)s * 21504u;
        const uint32_t vb = base + 43008u + (uint32_t)s * 17408u;

        // ---- scores ----
        float sf[8][4];
#pragma unroll
        for (int j = 0; j < 8; j++)
#pragma unroll
            for (int r = 0; r < 4; r++) sf[j][r] = 0.0f;

#pragma unroll
        for (int jn = 0; jn < 8; jn++) {
            const uint32_t baddr = kb + (uint32_t)(jn * 8 + (lane & 7)) * QPB + ((lane >> 3) & 1) * 16;
#pragma unroll
            for (int ka = 0; ka < 9; ka++) {
                uint32_t r0, r1, bh0, bl0, bh1, bl1;
                ldsm2(r0, r1, baddr + ka * 32);
                split_tf32(r0, bh0, bl0);
                split_tf32(r1, bh1, bl1);
                mma_tf32(sf[jn], qh[ka], bh0, bh1);
                mma_tf32(sf[jn], qh[ka], bl0, bl1);
                mma_tf32(sf[jn], ql[ka], bh0, bh1);
            }
        }

        // ---- online softmax ----
        float tmax0 = -INFINITY, tmax1 = -INFINITY;
#pragma unroll
        for (int j = 0; j < 8; j++) {
            sf[j][0] *= temp; sf[j][1] *= temp; sf[j][2] *= temp; sf[j][3] *= temp;
            tmax0 = fmaxf(tmax0, fmaxf(sf[j][0], sf[j][1]));
            tmax1 = fmaxf(tmax1, fmaxf(sf[j][2], sf[j][3]));
        }
        tmax0 = fmaxf(tmax0, __shfl_xor_sync(0xffffffffu, tmax0, 1));
        tmax0 = fmaxf(tmax0, __shfl_xor_sync(0xffffffffu, tmax0, 2));
        tmax1 = fmaxf(tmax1, __shfl_xor_sync(0xffffffffu, tmax1, 1));
        tmax1 = fmaxf(tmax1, __shfl_xor_sync(0xffffffffu, tmax1, 2));

        const float mn0 = fmaxf(m0, tmax0), mn1 = fmaxf(m1, tmax1);
        const float sc0 = __expf(m0 - mn0), sc1 = __expf(m1 - mn1);
        m0 = mn0; m1 = mn1;

        float ts0 = 0.f, ts1 = 0.f;
#pragma unroll
        for (int j = 0; j < 8; j++) {
            sf[j][0] = __expf(sf[j][0] - mn0);
            sf[j][1] = __expf(sf[j][1] - mn0);
            sf[j][2] = __expf(sf[j][2] - mn1);
            sf[j][3] = __expf(sf[j][3] - mn1);
            ts0 += sf[j][0] + sf[j][1];
            ts1 += sf[j][2] + sf[j][3];
        }
        ts0 += __shfl_xor_sync(0xffffffffu, ts0, 1);
        ts0 += __shfl_xor_sync(0xffffffffu, ts0, 2);
        ts1 += __shfl_xor_sync(0xffffffffu, ts1, 1);
        ts1 += __shfl_xor_sync(0xffffffffu, ts1, 2);
        l0 = l0 * sc0 + ts0;
        l1 = l1 * sc1 + ts1;

#pragma unroll
        for (int j = 0; j < 8; j++) {
            of[j][0] *= sc0; of[j][1] *= sc0; of[j][2] *= sc1; of[j][3] *= sc1;
        }

        // ---- P to per-warp smem, re-enter as A operand ----
#pragma unroll
        for (int j = 0; j < 8; j++) {
            uint32_t col = (uint32_t)(j * 8 + 2 * qq) * 4;
            sts64(pw + (uint32_t)rquad * VPB + col, sf[j][0], sf[j][1]);
            sts64(pw + (uint32_t)(rquad + 8) * VPB + col, sf[j][2], sf[j][3]);
        }
        __syncwarp();

#pragma unroll
        for (int ka = 0; ka < 8; ka++) {
            uint32_t r0, r1, r2, r3;
            ldsm4(r0, r1, r2, r3, pw + offAP + ka * 32);
            uint32_t ph[4], pl[4];
            split_tf32(r0, ph[0], pl[0]);
            split_tf32(r1, ph[1], pl[1]);
            split_tf32(r2, ph[2], pl[2]);
            split_tf32(r3, ph[3], pl[3]);
#pragma unroll
            for (int jn = 0; jn < 8; jn++) {
                uint32_t v0, v1, vh0, vl0, vh1, vl1;
                ldsm2(v0, v1, vb + (uint32_t)(jn * 8 + (lane & 7)) * VPB + ((lane >> 3) & 1) * 16 + ka * 32);
                split_tf32(v0, vh0, vl0);
                split_tf32(v1, vh1, vl1);
                mma_tf32(of[jn], ph, vh0, vh1);
                mma_tf32(of[jn], ph, vl0, vl1);
                mma_tf32(of[jn], pl, vh0, vh1);
            }
        }

        __syncthreads();   // stage s fully consumed before refill
        const int nxt = kt + 2;
        if (nxt < 32) load_tile(nxt, s);
        else cp_commit();
    }

    // ---- epilogue ----
    const float inv0 = 1.0f / l0, inv1 = 1.0f / l1;
    const int t0 = q0 + wid * 16 + rquad;
#pragma unroll
    for (int j = 0; j < 8; j++) {
        const int col = h * 64 + j * 8 + 2 * qq;
        *(float2*)&g_AO[(size_t)(b * Tv + t0) * Dv + col] =
            make_float2(of[j][0] * inv0, of[j][1] * inv0);
        *(float2*)&g_AO[(size_t)(b * Tv + t0 + 8) * Dv + col] =
            make_float2(of[j][2] * inv1, of[j][3] * inv1);
    }
}

// ---------------------------------------------------------------------------
extern "C" void kernel_launch(void* const* d_in, const int* in_sizes, int n_in,
                              void* d_out, int out_size) {
    const float* x   = (const float*)d_in[0];
    const float* Wq  = (const float*)d_in[1];
    const float* bq  = (const float*)d_in[2];
    const float* Wk  = (const float*)d_in[3];
    const float* bk  = (const float*)d_in[4];
    const float* Wv  = (const float*)d_in[5];
    const float* bv  = (const float*)d_in[6];
    const float* Wo  = (const float*)d_in[7];
    const float* bo  = (const float*)d_in[8];
    const float* Wqs = (const float*)d_in[9];
    const float* bqs = (const float*)d_in[10];
    const float* Wks = (const float*)d_in[11];
    const float* bks = (const float*)d_in[12];
    const float* Wvs = (const float*)d_in[13];
    const float* bvs = (const float*)d_in[14];
    const float* temp = (const float*)d_in[15];

    float *gQe, *gKe, *gV, *gVt, *gAO;
    cudaGetSymbolAddress((void**)&gQe, g_Qe);
    cudaGetSymbolAddress((void**)&gKe, g_Ke);
    cudaGetSymbolAddress((void**)&gV, g_V);
    cudaGetSymbolAddress((void**)&gVt, g_Vt);
    cudaGetSymbolAddress((void**)&gAO, g_AO);

    const int dyn_smem = 4 * STAGE_BYTES;   // 73728
    cudaFuncSetAttribute(gemm_mma<0>, cudaFuncAttributeMaxDynamicSharedMemorySize, dyn_smem);
    cudaFuncSetAttribute(gemm_mma<1>, cudaFuncAttributeMaxDynamicSharedMemorySize, dyn_smem);
    cudaFuncSetAttribute(gemm_mma<2>, cudaFuncAttributeMaxDynamicSharedMemorySize, dyn_smem);
    cudaFuncSetAttribute(attn_mma, cudaFuncAttributeMaxDynamicSharedMemorySize, ATT_SMEM);

    dim3 ggrid(Dv / 128, Mv / 128);   // (8, 32)
    gemm_mma<1><<<ggrid, 256, dyn_smem>>>(x, Wq, bq, gQe, nullptr);
    gemm_mma<1><<<ggrid, 256, dyn_smem>>>(x, Wk, bk, gKe, nullptr);
    gemm_mma<2><<<ggrid, 256, dyn_smem>>>(x, Wv, bv, gVt, gV);

    int nwarps = Bv * Hv * Tv;                 // 65536
    stp_kernel<<<nwarps / 8, 256>>>(Wqs, bqs, Wks, bks, Wvs, bvs);

    dim3 agrid(Tv / 128, Hv, Bv);              // (16, 16, 2)
    attn_mma<<<agrid, 256, ATT_SMEM>>>(temp);

    gemm_mma<0><<<ggrid, 256, dyn_smem>>>(gAO, Wo, bo, (float*)d_out, nullptr);
}

// round 8
// speedup vs baseline: 2.8785x; 1.1499x over previous
#include <cuda_runtime.h>
#include <math.h>
#include <stdint.h>

#define Bv 2
#define Tv 2048
#define Dv 1024
#define Hv 16
#define HDv 64
#define Mv (Bv * Tv)   // 4096

// Scratch (allocation-free rule: __device__ globals)
__device__ float g_Qe[Bv * Hv * Tv * 80];   // [b,h,t,80]: 0-63 q, 64-66 qs, 67-71 zero
__device__ float g_Ke[Bv * Hv * Tv * 80];   // [b,h,t,80]: 0-63 k, 64-66 ckv, 67-71 zero
__device__ float g_V [Bv * Hv * Tv * HDv];  // [b,h,t,hd]
__device__ float g_Vt[Bv * Hv * HDv * Tv];  // [b,h,hd,t] (transposed for PV mma)
__device__ float g_AO[Bv * Tv * Dv];        // attention out, [b,t,h*HD+hd]

// ======================= base-ISA helpers (sm_80-class) =====================
__device__ __forceinline__ uint32_t smem_u32(const void* p) {
    uint32_t a;
    asm("{ .reg .u64 t; cvta.to.shared.u64 t, %1; cvt.u32.u64 %0, t; }" : "=r"(a) : "l"(p));
    return a;
}
__device__ __forceinline__ void cp16(uint32_t dst, const void* src) {
    asm volatile("cp.async.cg.shared.global [%0], [%1], 16;" :: "r"(dst), "l"(src) : "memory");
}
__device__ __forceinline__ void cp_commit() {
    asm volatile("cp.async.commit_group;" ::: "memory");
}
template <int N>
__device__ __forceinline__ void cp_wait() {
    asm volatile("cp.async.wait_group %0;" :: "n"(N) : "memory");
}
__device__ __forceinline__ void ldsm4(uint32_t& r0, uint32_t& r1, uint32_t& r2, uint32_t& r3,
                                      uint32_t addr) {
    asm volatile("ldmatrix.sync.aligned.m8n8.x4.shared.b16 {%0,%1,%2,%3}, [%4];"
                 : "=r"(r0), "=r"(r1), "=r"(r2), "=r"(r3) : "r"(addr));
}
__device__ __forceinline__ void ldsm2(uint32_t& r0, uint32_t& r1, uint32_t addr) {
    asm volatile("ldmatrix.sync.aligned.m8n8.x2.shared.b16 {%0,%1}, [%2];"
                 : "=r"(r0), "=r"(r1) : "r"(addr));
}
__device__ __forceinline__ void sts64(uint32_t addr, float x, float y) {
    asm volatile("st.shared.v2.f32 [%0], {%1,%2};" :: "r"(addr), "f"(x), "f"(y) : "memory");
}
__device__ __forceinline__ void mma_tf32(float* d, const uint32_t* a, uint32_t b0, uint32_t b1) {
    asm volatile(
        "mma.sync.aligned.m16n8k8.row.col.f32.tf32.tf32.f32 "
        "{%0,%1,%2,%3}, {%4,%5,%6,%7}, {%8,%9}, {%0,%1,%2,%3};"
        : "+f"(d[0]), "+f"(d[1]), "+f"(d[2]), "+f"(d[3])
        : "r"(a[0]), "r"(a[1]), "r"(a[2]), "r"(a[3]), "r"(b0), "r"(b1));
}
// 3xTF32 split: hi = tf32(x), lo = tf32(x - hi)
__device__ __forceinline__ void split_tf32(uint32_t raw, uint32_t& hi, uint32_t& lo) {
    float f = __uint_as_float(raw);
    asm("cvt.rna.tf32.f32 %0, %1;" : "=r"(hi) : "f"(f));
    float r = f - __uint_as_float(hi);
    asm("cvt.rna.tf32.f32 %0, %1;" : "=r"(lo) : "f"(r));
}
// single-pass tf32 round (hi only)
__device__ __forceinline__ uint32_t tf32_hi(uint32_t raw) {
    uint32_t hi;
    asm("cvt.rna.tf32.f32 %0, %1;" : "=r"(hi) : "f"(__uint_as_float(raw)));
    return hi;
}
__device__ __forceinline__ uint32_t tf32_hif(float f) {
    uint32_t hi;
    asm("cvt.rna.tf32.f32 %0, %1;" : "=r"(hi) : "f"(f));
    return hi;
}

// ---------------------------------------------------------------------------
// 3xTF32 mma.sync GEMM: C[m,n] = sum_k X[m,k] * W[n,k] + bias[n]
// MODE 0: plain row-major out. MODE 1: head-split extended pitch-80 (Q/K).
// MODE 2: V dual-write (transposed g_Vt to out, head-split to out2).
// ---------------------------------------------------------------------------
#define PITCH 36
#define PITCHB (PITCH * 4)           // 144 bytes
#define STAGE_BYTES (128 * PITCHB)   // 18432
#define KCH 32
#define NSTEP (1024 / KCH)           // 32

template <int MODE>
__global__ __launch_bounds__(256) void gemm_mma(const float* __restrict__ X,
                                                const float* __restrict__ W,
                                                const float* __restrict__ bias,
                                                float* __restrict__ out,
                                                float* __restrict__ out2) {
    extern __shared__ char dsm[];
    const uint32_t sbase = smem_u32(dsm);
    const int K = 1024;
    const int n0 = blockIdx.x * 128;
    const int m0 = blockIdx.y * 128;
    const int tid = threadIdx.x;
    const int lane = tid & 31;
    const int wid = tid >> 5;
    const int wm = wid >> 2;
    const int wn = wid & 3;

    uint32_t Ab[2], Wb[2];
    Ab[0] = sbase;                     Wb[0] = sbase + STAGE_BYTES;
    Ab[1] = sbase + 2 * STAGE_BYTES;   Wb[1] = sbase + 3 * STAGE_BYTES;

    const uint32_t offA = ((lane & 7) + ((lane >> 3) & 1) * 8) * PITCHB + ((lane >> 4) & 1) * 16;
    const uint32_t offB = (lane & 7) * PITCHB + ((lane >> 3) & 1) * 16;
    const uint32_t aWarp = (uint32_t)(wm * 64) * PITCHB + offA;
    const uint32_t bWarp = (uint32_t)(wn * 32) * PITCHB + offB;

    const int lrow0 = tid >> 3;
    const int lc4 = (tid & 7) * 16;

    float acc[4][4][4];
#pragma unroll
    for (int i = 0; i < 4; i++)
#pragma unroll
        for (int j = 0; j < 4; j++)
#pragma unroll
            for (int r = 0; r < 4; r++) acc[i][j][r] = 0.0f;

#pragma unroll
    for (int s = 0; s < 2; s++) {
        const int k0 = s * KCH;
#pragma unroll
        for (int it = 0; it < 4; it++) {
            int row = lrow0 + it * 32;
            cp16(Ab[s] + (uint32_t)row * PITCHB + lc4, &X[(size_t)(m0 + row) * K + k0] + (lc4 >> 2));
            cp16(Wb[s] + (uint32_t)row * PITCHB + lc4, &W[(size_t)(n0 + row) * K + k0] + (lc4 >> 2));
        }
        cp_commit();
    }

    for (int c = 0; c < NSTEP; c++) {
        cp_wait<1>();
        __syncthreads();
        const int s = c & 1;
        const uint32_t Abase = Ab[s] + aWarp;
        const uint32_t Bbase = Wb[s] + bWarp;

#pragma unroll
        for (int ka = 0; ka < 4; ka++) {
            uint32_t bh0[4], bh1[4], bl0[4], bl1[4];
#pragma unroll
            for (int jn = 0; jn < 4; jn++) {
                uint32_t r0, r1;
                ldsm2(r0, r1, Bbase + (uint32_t)(jn * 8) * PITCHB + ka * 32);
                split_tf32(r0, bh0[jn], bl0[jn]);
                split_tf32(r1, bh1[jn], bl1[jn]);
            }
#pragma unroll
            for (int i = 0; i < 4; i++) {
                uint32_t r0, r1, r2, r3;
                ldsm4(r0, r1, r2, r3, Abase + (uint32_t)(i * 16) * PITCHB + ka * 32);
                uint32_t ah[4], al[4];
                split_tf32(r0, ah[0], al[0]);
                split_tf32(r1, ah[1], al[1]);
                split_tf32(r2, ah[2], al[2]);
                split_tf32(r3, ah[3], al[3]);
#pragma unroll
                for (int jn = 0; jn < 4; jn++) {
                    mma_tf32(acc[i][jn], ah, bh0[jn], bh1[jn]);
                    mma_tf32(acc[i][jn], ah, bl0[jn], bl1[jn]);
                    mma_tf32(acc[i][jn], al, bh0[jn], bh1[jn]);
                }
            }
        }
        __syncthreads();

        const int nxt = c + 2;
        if (nxt < NSTEP) {
            const int k0 = nxt * KCH;
#pragma unroll
            for (int it = 0; it < 4; it++) {
                int row = lrow0 + it * 32;
                cp16(Ab[s] + (uint32_t)row * PITCHB + lc4, &X[(size_t)(m0 + row) * K + k0] + (lc4 >> 2));
                cp16(Wb[s] + (uint32_t)row * PITCHB + lc4, &W[(size_t)(n0 + row) * K + k0] + (lc4 >> 2));
            }
        }
        cp_commit();
    }

#pragma unroll
    for (int i = 0; i < 4; i++) {
        const int mlo = m0 + wm * 64 + i * 16 + (lane >> 2);
#pragma unroll
        for (int jn = 0; jn < 4; jn++) {
            const int nb = n0 + wn * 32 + jn * 8 + (lane & 3) * 2;
            const float2 bb = *(const float2*)&bias[nb];
            float2 v0 = make_float2(acc[i][jn][0] + bb.x, acc[i][jn][1] + bb.y);
            float2 v1 = make_float2(acc[i][jn][2] + bb.x, acc[i][jn][3] + bb.y);
#pragma unroll
            for (int u = 0; u < 2; u++) {
                const int m = mlo + u * 8;
                const float2 v = (u == 0) ? v0 : v1;
                if (MODE == 0) {
                    *(float2*)&out[(size_t)m * Dv + nb] = v;
                } else if (MODE == 1) {
                    int b = m >> 11, t = m & 2047;
                    int h = nb >> 6, hd = nb & 63;
                    *(float2*)&out[((size_t)(b * Hv + h) * Tv + t) * 80 + hd] = v;
                } else {
                    int b = m >> 11, t = m & 2047;
                    int h = nb >> 6, hd = nb & 63;
                    size_t vt = ((size_t)((b * Hv + h) * HDv + hd)) * Tv + t;
                    out[vt] = v.x;
                    out[vt + Tv] = v.y;
                    *(float2*)&out2[(((size_t)(b * Hv + h) * Tv) + t) * HDv + hd] = v;
                }
            }
        }
    }
}

// ---------------------------------------------------------------------------
// STP: per (b,h,t) row, compute q_stp[3] and cross(k3, v3)[3]; write into the
// extended cols (64..71) of g_Qe / g_Ke. One warp/row.
// ---------------------------------------------------------------------------
__global__ __launch_bounds__(256) void stp_kernel(const float* __restrict__ Wqs,
                                                  const float* __restrict__ bqs,
                                                  const float* __restrict__ Wks,
                                                  const float* __restrict__ bks,
                                                  const float* __restrict__ Wvs,
                                                  const float* __restrict__ bvs) {
    int warp = (blockIdx.x * blockDim.x + threadIdx.x) >> 5;
    int lane = threadIdx.x & 31;
    if (warp >= Bv * Hv * Tv) return;

    const float* q = g_Qe + (size_t)warp * 80;
    const float* k = g_Ke + (size_t)warp * 80;
    const float* v = g_V + (size_t)warp * HDv;

    float q0 = q[lane], q1 = q[lane + 32];
    float k0 = k[lane], k1 = k[lane + 32];
    float v0 = v[lane], v1 = v[lane + 32];

    float qs[3], k3[3], v3[3];
#pragma unroll
    for (int c = 0; c < 3; c++) {
        float pq = q0 * Wqs[c * HDv + lane] + q1 * Wqs[c * HDv + lane + 32];
        float pk = k0 * Wks[c * HDv + lane] + k1 * Wks[c * HDv + lane + 32];
        float pv = v0 * Wvs[c * HDv + lane] + v1 * Wvs[c * HDv + lane + 32];
#pragma unroll
        for (int o = 16; o > 0; o >>= 1) {
            pq += __shfl_xor_sync(0xffffffffu, pq, o);
            pk += __shfl_xor_sync(0xffffffffu, pk, o);
            pv += __shfl_xor_sync(0xffffffffu, pv, o);
        }
        qs[c] = pq + bqs[c];
        k3[c] = pk + bks[c];
        v3[c] = pv + bvs[c];
    }

    if (lane == 0) {
        float4* qe = (float4*)(g_Qe + (size_t)warp * 80 + 64);
        qe[0] = make_float4(qs[0], qs[1], qs[2], 0.f);
        qe[1] = make_float4(0.f, 0.f, 0.f, 0.f);
        float c0 = k3[1] * v3[2] - k3[2] * v3[1];
        float c1 = k3[2] * v3[0] - k3[0] * v3[2];
        float c2 = k3[0] * v3[1] - k3[1] * v3[0];
        float4* ke = (float4*)(g_Ke + (size_t)warp * 80 + 64);
        ke[0] = make_float4(c0, c1, c2, 0.f);
        ke[1] = make_float4(0.f, 0.f, 0.f, 0.f);
    }
}

// ---------------------------------------------------------------------------
// mma.sync flash attention. CTA = 128 q-rows of one head; 8 warps x 16 rows.
// S = Qe(72) . Ke(72)^T via 3xTF32 (softmax-sensitive); online softmax;
// O += P.V via SINGLE-pass tf32 (linear path, error budget allows).
// Smem: K stages [0, 43008), V stages [43008, 77824), P [77824, 112640).
// ---------------------------------------------------------------------------
#define QPB 336   // Q/K smem pitch bytes (84 floats; 336 % 128 = 80 -> conflict-free)
#define VPB 272   // V/P smem pitch bytes (68 floats; 272 % 128 = 16 -> conflict-free)
#define ATT_SMEM 112640

__global__ __launch_bounds__(256, 1) void attn_mma(const float* __restrict__ temp_p) {
    extern __shared__ char dsm[];
    const uint32_t base = smem_u32(dsm);
    const int b = blockIdx.z, h = blockIdx.y;
    const int q0 = blockIdx.x * 128;
    const int tid = threadIdx.x, lane = tid & 31, wid = tid >> 5;
    const float temp = *temp_p;

    const float* Qe = g_Qe + ((size_t)(b * Hv + h) * Tv + q0) * 80;
    const float* Ke = g_Ke + (size_t)(b * Hv + h) * Tv * 80;
    const float* Vt = g_Vt + (size_t)(b * Hv + h) * HDv * Tv;

    // ---- stage Q (borrow K region), split to registers ----
#pragma unroll
    for (int i = 0; i < 10; i++) {
        int idx = tid + i * 256;
        int row = idx / 20, c = idx % 20;
        cp16(base + (uint32_t)row * QPB + c * 16, Qe + row * 80 + c * 4);
    }
    cp_commit();
    cp_wait<0>();
    __syncthreads();

    uint32_t qh[9][4], ql[9][4];
    {
        const uint32_t qa = base + (uint32_t)(wid * 16) * QPB +
            ((lane & 7) + ((lane >> 3) & 1) * 8) * QPB + ((lane >> 4) & 1) * 16;
#pragma unroll
        for (int ka = 0; ka < 9; ka++) {
            uint32_t r0, r1, r2, r3;
            ldsm4(r0, r1, r2, r3, qa + ka * 32);
            split_tf32(r0, qh[ka][0], ql[ka][0]);
            split_tf32(r1, qh[ka][1], ql[ka][1]);
            split_tf32(r2, qh[ka][2], ql[ka][2]);
            split_tf32(r3, qh[ka][3], ql[ka][3]);
        }
    }
    __syncthreads();   // Q staging area free before K loads

    float of[8][4];
#pragma unroll
    for (int j = 0; j < 8; j++)
#pragma unroll
        for (int r = 0; r < 4; r++) of[j][r] = 0.0f;
    float m0 = -INFINITY, m1 = -INFINITY, l0 = 0.f, l1 = 0.f;

    auto load_tile = [&](int kt, int s) {
        uint32_t kb = base + (uint32_t)s * 21504u;
#pragma unroll
        for (int i = 0; i < 5; i++) {
            int idx = tid + i * 256;
            int row = idx / 20, c = idx % 20;
            cp16(kb + (uint32_t)row * QPB + c * 16, Ke + (size_t)(kt * 64 + row) * 80 + c * 4);
        }
        uint32_t vb = base + 43008u + (uint32_t)s * 17408u;
#pragma unroll
        for (int i = 0; i < 4; i++) {
            int idx = tid + i * 256;
            int row = idx >> 4, c = idx & 15;
            cp16(vb + (uint32_t)row * VPB + c * 16, Vt + (size_t)row * Tv + kt * 64 + c * 4);
        }
        cp_commit();
    };

    load_tile(0, 0);
    load_tile(1, 1);

    const uint32_t pw = base + 77824u + (uint32_t)wid * 4352u;
    const uint32_t offAP = ((lane & 7) + ((lane >> 3) & 1) * 8) * VPB + ((lane >> 4) & 1) * 16;
    const int rquad = lane >> 2, qq = lane & 3;

    for (int kt = 0; kt < 32; kt++) {
        cp_wait<1>();
        __syncthreads();
        const int s = kt & 1;
        const uint32_t kb = base + (uint32_t)s * 21504u;
        const uint32_t vb = base + 43008u + (uint32_t)s * 17408u;

        // ---- scores (3xTF32) ----
        float sf[8][4];
#pragma unroll
        for (int j = 0; j < 8; j++)
#pragma unroll
            for (int r = 0; r < 4; r++) sf[j][r] = 0.0f;

#pragma unroll
        for (int jn = 0; jn < 8; jn++) {
            const uint32_t baddr = kb + (uint32_t)(jn * 8 + (lane & 7)) * QPB + ((lane >> 3) & 1) * 16;
#pragma unroll
            for (int ka = 0; ka < 9; ka++) {
                uint32_t r0, r1, bh0, bl0, bh1, bl1;
                ldsm2(r0, r1, baddr + ka * 32);
                split_tf32(r0, bh0, bl0);
                split_tf32(r1, bh1, bl1);
                mma_tf32(sf[jn], qh[ka], bh0, bh1);
                mma_tf32(sf[jn], qh[ka], bl0, bl1);
                mma_tf32(sf[jn], ql[ka], bh0, bh1);
            }
        }

        // ---- online softmax ----
        float tmax0 = -INFINITY, tmax1 = -INFINITY;
#pragma unroll
        for (int j = 0; j < 8; j++) {
            sf[j][0] *= temp; sf[j][1] *= temp; sf[j][2] *= temp; sf[j][3] *= temp;
            tmax0 = fmaxf(tmax0, fmaxf(sf[j][0], sf[j][1]));
            tmax1 = fmaxf(tmax1, fmaxf(sf[j][2], sf[j][3]));
        }
        tmax0 = fmaxf(tmax0, __shfl_xor_sync(0xffffffffu, tmax0, 1));
        tmax0 = fmaxf(tmax0, __shfl_xor_sync(0xffffffffu, tmax0, 2));
        tmax1 = fmaxf(tmax1, __shfl_xor_sync(0xffffffffu, tmax1, 1));
        tmax1 = fmaxf(tmax1, __shfl_xor_sync(0xffffffffu, tmax1, 2));

        const float mn0 = fmaxf(m0, tmax0), mn1 = fmaxf(m1, tmax1);
        const float sc0 = __expf(m0 - mn0), sc1 = __expf(m1 - mn1);
        m0 = mn0; m1 = mn1;

        float ts0 = 0.f, ts1 = 0.f;
#pragma unroll
        for (int j = 0; j < 8; j++) {
            sf[j][0] = __expf(sf[j][0] - mn0);
            sf[j][1] = __expf(sf[j][1] - mn0);
            sf[j][2] = __expf(sf[j][2] - mn1);
            sf[j][3] = __expf(sf[j][3] - mn1);
            ts0 += sf[j][0] + sf[j][1];
            ts1 += sf[j][2] + sf[j][3];
        }
        ts0 += __shfl_xor_sync(0xffffffffu, ts0, 1);
        ts0 += __shfl_xor_sync(0xffffffffu, ts0, 2);
        ts1 += __shfl_xor_sync(0xffffffffu, ts1, 1);
        ts1 += __shfl_xor_sync(0xffffffffu, ts1, 2);
        l0 = l0 * sc0 + ts0;
        l1 = l1 * sc1 + ts1;

#pragma unroll
        for (int j = 0; j < 8; j++) {
            of[j][0] *= sc0; of[j][1] *= sc0; of[j][2] *= sc1; of[j][3] *= sc1;
        }

        // ---- P to per-warp smem, re-enter as A operand ----
#pragma unroll
        for (int j = 0; j < 8; j++) {
            uint32_t col = (uint32_t)(j * 8 + 2 * qq) * 4;
            sts64(pw + (uint32_t)rquad * VPB + col, sf[j][0], sf[j][1]);
            sts64(pw + (uint32_t)(rquad + 8) * VPB + col, sf[j][2], sf[j][3]);
        }
        __syncwarp();

        // ---- PV (single-pass tf32) ----
#pragma unroll
        for (int ka = 0; ka < 8; ka++) {
            uint32_t r0, r1, r2, r3;
            ldsm4(r0, r1, r2, r3, pw + offAP + ka * 32);
            uint32_t ph[4];
            ph[0] = tf32_hi(r0);
            ph[1] = tf32_hi(r1);
            ph[2] = tf32_hi(r2);
            ph[3] = tf32_hi(r3);
#pragma unroll
            for (int jn = 0; jn < 8; jn++) {
                uint32_t v0, v1;
                ldsm2(v0, v1, vb + (uint32_t)(jn * 8 + (lane & 7)) * VPB + ((lane >> 3) & 1) * 16 + ka * 32);
                mma_tf32(of[jn], ph, tf32_hi(v0), tf32_hi(v1));
            }
        }

        __syncthreads();   // stage s fully consumed before refill
        const int nxt = kt + 2;
        if (nxt < 32) load_tile(nxt, s);
        else cp_commit();
    }

    // ---- epilogue ----
    const float inv0 = 1.0f / l0, inv1 = 1.0f / l1;
    const int t0 = q0 + wid * 16 + rquad;
#pragma unroll
    for (int j = 0; j < 8; j++) {
        const int col = h * 64 + j * 8 + 2 * qq;
        *(float2*)&g_AO[(size_t)(b * Tv + t0) * Dv + col] =
            make_float2(of[j][0] * inv0, of[j][1] * inv0);
        *(float2*)&g_AO[(size_t)(b * Tv + t0 + 8) * Dv + col] =
            make_float2(of[j][2] * inv1, of[j][3] * inv1);
    }
}

// ---------------------------------------------------------------------------
extern "C" void kernel_launch(void* const* d_in, const int* in_sizes, int n_in,
                              void* d_out, int out_size) {
    const float* x   = (const float*)d_in[0];
    const float* Wq  = (const float*)d_in[1];
    const float* bq  = (const float*)d_in[2];
    const float* Wk  = (const float*)d_in[3];
    const float* bk  = (const float*)d_in[4];
    const float* Wv  = (const float*)d_in[5];
    const float* bv  = (const float*)d_in[6];
    const float* Wo  = (const float*)d_in[7];
    const float* bo  = (const float*)d_in[8];
    const float* Wqs = (const float*)d_in[9];
    const float* bqs = (const float*)d_in[10];
    const float* Wks = (const float*)d_in[11];
    const float* bks = (const float*)d_in[12];
    const float* Wvs = (const float*)d_in[13];
    const float* bvs = (const float*)d_in[14];
    const float* temp = (const float*)d_in[15];

    float *gQe, *gKe, *gV, *gVt, *gAO;
    cudaGetSymbolAddress((void**)&gQe, g_Qe);
    cudaGetSymbolAddress((void**)&gKe, g_Ke);
    cudaGetSymbolAddress((void**)&gV, g_V);
    cudaGetSymbolAddress((void**)&gVt, g_Vt);
    cudaGetSymbolAddress((void**)&gAO, g_AO);

    const int dyn_smem = 4 * STAGE_BYTES;   // 73728
    cudaFuncSetAttribute(gemm_mma<0>, cudaFuncAttributeMaxDynamicSharedMemorySize, dyn_smem);
    cudaFuncSetAttribute(gemm_mma<1>, cudaFuncAttributeMaxDynamicSharedMemorySize, dyn_smem);
    cudaFuncSetAttribute(gemm_mma<2>, cudaFuncAttributeMaxDynamicSharedMemorySize, dyn_smem);
    cudaFuncSetAttribute(attn_mma, cudaFuncAttributeMaxDynamicSharedMemorySize, ATT_SMEM);

    dim3 ggrid(Dv / 128, Mv / 128);   // (8, 32)
    gemm_mma<1><<<ggrid, 256, dyn_smem>>>(x, Wq, bq, gQe, nullptr);
    gemm_mma<1><<<ggrid, 256, dyn_smem>>>(x, Wk, bk, gKe, nullptr);
    gemm_mma<2><<<ggrid, 256, dyn_smem>>>(x, Wv, bv, gVt, gV);

    int nwarps = Bv * Hv * Tv;                 // 65536
    stp_kernel<<<nwarps / 8, 256>>>(Wqs, bqs, Wks, bks, Wvs, bvs);

    dim3 agrid(Tv / 128, Hv, Bv);              // (16, 16, 2)
    attn_mma<<<agrid, 256, ATT_SMEM>>>(temp);

    gemm_mma<0><<<ggrid, 256, dyn_smem>>>(gAO, Wo, bo, (float*)d_out, nullptr);
}

// round 9
// speedup vs baseline: 3.0765x; 1.0688x over previous
#include <cuda_runtime.h>
#include <math.h>
#include <stdint.h>

#define Bv 2
#define Tv 2048
#define Dv 1024
#define Hv 16
#define HDv 64
#define Mv (Bv * Tv)   // 4096

// Scratch (allocation-free rule: __device__ globals; zero-initialized at load)
__device__ float g_Qe [Bv * Hv * Tv * 80];  // [b,h,t,80]: 0-63 q, 64-66 qs, 67-79 zero
__device__ float g_KeH[Bv * Hv * Tv * 80];  // tf32-hi of k / cross_kv
__device__ float g_KeL[Bv * Hv * Tv * 80];  // tf32-lo residual
__device__ float g_V  [Bv * Hv * Tv * HDv]; // [b,h,t,hd] full precision (for stp)
__device__ float g_Vt [Bv * Hv * HDv * Tv]; // [b,h,hd,t] tf32-rounded (for PV mma)
__device__ float g_AO [Bv * Tv * Dv];       // attention out, [b,t,h*HD+hd]

// ======================= base-ISA helpers (sm_80-class) =====================
__device__ __forceinline__ uint32_t smem_u32(const void* p) {
    uint32_t a;
    asm("{ .reg .u64 t; cvta.to.shared.u64 t, %1; cvt.u32.u64 %0, t; }" : "=r"(a) : "l"(p));
    return a;
}
__device__ __forceinline__ void cp16(uint32_t dst, const void* src) {
    asm volatile("cp.async.cg.shared.global [%0], [%1], 16;" :: "r"(dst), "l"(src) : "memory");
}
__device__ __forceinline__ void cp_commit() {
    asm volatile("cp.async.commit_group;" ::: "memory");
}
template <int N>
__device__ __forceinline__ void cp_wait() {
    asm volatile("cp.async.wait_group %0;" :: "n"(N) : "memory");
}
__device__ __forceinline__ void ldsm4(uint32_t& r0, uint32_t& r1, uint32_t& r2, uint32_t& r3,
                                      uint32_t addr) {
    asm volatile("ldmatrix.sync.aligned.m8n8.x4.shared.b16 {%0,%1,%2,%3}, [%4];"
                 : "=r"(r0), "=r"(r1), "=r"(r2), "=r"(r3) : "r"(addr));
}
__device__ __forceinline__ void ldsm2(uint32_t& r0, uint32_t& r1, uint32_t addr) {
    asm volatile("ldmatrix.sync.aligned.m8n8.x2.shared.b16 {%0,%1}, [%2];"
                 : "=r"(r0), "=r"(r1) : "r"(addr));
}
__device__ __forceinline__ void sts64(uint32_t addr, float x, float y) {
    asm volatile("st.shared.v2.f32 [%0], {%1,%2};" :: "r"(addr), "f"(x), "f"(y) : "memory");
}
__device__ __forceinline__ void mma_tf32(float* d, const uint32_t* a, uint32_t b0, uint32_t b1) {
    asm volatile(
        "mma.sync.aligned.m16n8k8.row.col.f32.tf32.tf32.f32 "
        "{%0,%1,%2,%3}, {%4,%5,%6,%7}, {%8,%9}, {%0,%1,%2,%3};"
        : "+f"(d[0]), "+f"(d[1]), "+f"(d[2]), "+f"(d[3])
        : "r"(a[0]), "r"(a[1]), "r"(a[2]), "r"(a[3]), "r"(b0), "r"(b1));
}
// 3xTF32 split: hi = tf32(x), lo = tf32(x - hi)
__device__ __forceinline__ void split_tf32(uint32_t raw, uint32_t& hi, uint32_t& lo) {
    float f = __uint_as_float(raw);
    asm("cvt.rna.tf32.f32 %0, %1;" : "=r"(hi) : "f"(f));
    float r = f - __uint_as_float(hi);
    asm("cvt.rna.tf32.f32 %0, %1;" : "=r"(lo) : "f"(r));
}
__device__ __forceinline__ uint32_t tf32_hi(uint32_t raw) {
    uint32_t hi;
    asm("cvt.rna.tf32.f32 %0, %1;" : "=r"(hi) : "f"(__uint_as_float(raw)));
    return hi;
}
__device__ __forceinline__ uint32_t tf32_hif(float f) {
    uint32_t hi;
    asm("cvt.rna.tf32.f32 %0, %1;" : "=r"(hi) : "f"(f));
    return hi;
}

// ---------------------------------------------------------------------------
// 3xTF32 mma.sync GEMM: C[m,n] = sum_k X[m,k] * W[n,k] + bias[n]
// MODE 0: plain row-major. MODE 1: Q head-split pitch-80 full precision.
// MODE 2: V dual-write (g_Vt transposed tf32-rounded, g_V full head-split).
// MODE 3: K head-split pitch-80 hi/lo dual arrays.
// ---------------------------------------------------------------------------
#define PITCH 36
#define PITCHB (PITCH * 4)           // 144 bytes
#define STAGE_BYTES (128 * PITCHB)   // 18432
#define KCH 32
#define NSTEP (1024 / KCH)           // 32

template <int MODE>
__global__ __launch_bounds__(256) void gemm_mma(const float* __restrict__ X,
                                                const float* __restrict__ W,
                                                const float* __restrict__ bias,
                                                float* __restrict__ out,
                                                float* __restrict__ out2) {
    extern __shared__ char dsm[];
    const uint32_t sbase = smem_u32(dsm);
    const int K = 1024;
    const int n0 = blockIdx.x * 128;
    const int m0 = blockIdx.y * 128;
    const int tid = threadIdx.x;
    const int lane = tid & 31;
    const int wid = tid >> 5;
    const int wm = wid >> 2;
    const int wn = wid & 3;

    uint32_t Ab[2], Wb[2];
    Ab[0] = sbase;                     Wb[0] = sbase + STAGE_BYTES;
    Ab[1] = sbase + 2 * STAGE_BYTES;   Wb[1] = sbase + 3 * STAGE_BYTES;

    const uint32_t offA = ((lane & 7) + ((lane >> 3) & 1) * 8) * PITCHB + ((lane >> 4) & 1) * 16;
    const uint32_t offB = (lane & 7) * PITCHB + ((lane >> 3) & 1) * 16;
    const uint32_t aWarp = (uint32_t)(wm * 64) * PITCHB + offA;
    const uint32_t bWarp = (uint32_t)(wn * 32) * PITCHB + offB;

    const int lrow0 = tid >> 3;
    const int lc4 = (tid & 7) * 16;

    float acc[4][4][4];
#pragma unroll
    for (int i = 0; i < 4; i++)
#pragma unroll
        for (int j = 0; j < 4; j++)
#pragma unroll
            for (int r = 0; r < 4; r++) acc[i][j][r] = 0.0f;

#pragma unroll
    for (int s = 0; s < 2; s++) {
        const int k0 = s * KCH;
#pragma unroll
        for (int it = 0; it < 4; it++) {
            int row = lrow0 + it * 32;
            cp16(Ab[s] + (uint32_t)row * PITCHB + lc4, &X[(size_t)(m0 + row) * K + k0] + (lc4 >> 2));
            cp16(Wb[s] + (uint32_t)row * PITCHB + lc4, &W[(size_t)(n0 + row) * K + k0] + (lc4 >> 2));
        }
        cp_commit();
    }

    for (int c = 0; c < NSTEP; c++) {
        cp_wait<1>();
        __syncthreads();
        const int s = c & 1;
        const uint32_t Abase = Ab[s] + aWarp;
        const uint32_t Bbase = Wb[s] + bWarp;

#pragma unroll
        for (int ka = 0; ka < 4; ka++) {
            uint32_t bh0[4], bh1[4], bl0[4], bl1[4];
#pragma unroll
            for (int jn = 0; jn < 4; jn++) {
                uint32_t r0, r1;
                ldsm2(r0, r1, Bbase + (uint32_t)(jn * 8) * PITCHB + ka * 32);
                split_tf32(r0, bh0[jn], bl0[jn]);
                split_tf32(r1, bh1[jn], bl1[jn]);
            }
#pragma unroll
            for (int i = 0; i < 4; i++) {
                uint32_t r0, r1, r2, r3;
                ldsm4(r0, r1, r2, r3, Abase + (uint32_t)(i * 16) * PITCHB + ka * 32);
                uint32_t ah[4], al[4];
                split_tf32(r0, ah[0], al[0]);
                split_tf32(r1, ah[1], al[1]);
                split_tf32(r2, ah[2], al[2]);
                split_tf32(r3, ah[3], al[3]);
#pragma unroll
                for (int jn = 0; jn < 4; jn++) {
                    mma_tf32(acc[i][jn], ah, bh0[jn], bh1[jn]);
                    mma_tf32(acc[i][jn], ah, bl0[jn], bl1[jn]);
                    mma_tf32(acc[i][jn], al, bh0[jn], bh1[jn]);
                }
            }
        }
        __syncthreads();

        const int nxt = c + 2;
        if (nxt < NSTEP) {
            const int k0 = nxt * KCH;
#pragma unroll
            for (int it = 0; it < 4; it++) {
                int row = lrow0 + it * 32;
                cp16(Ab[s] + (uint32_t)row * PITCHB + lc4, &X[(size_t)(m0 + row) * K + k0] + (lc4 >> 2));
                cp16(Wb[s] + (uint32_t)row * PITCHB + lc4, &W[(size_t)(n0 + row) * K + k0] + (lc4 >> 2));
            }
        }
        cp_commit();
    }

#pragma unroll
    for (int i = 0; i < 4; i++) {
        const int mlo = m0 + wm * 64 + i * 16 + (lane >> 2);
#pragma unroll
        for (int jn = 0; jn < 4; jn++) {
            const int nb = n0 + wn * 32 + jn * 8 + (lane & 3) * 2;
            const float2 bb = *(const float2*)&bias[nb];
            float2 v0 = make_float2(acc[i][jn][0] + bb.x, acc[i][jn][1] + bb.y);
            float2 v1 = make_float2(acc[i][jn][2] + bb.x, acc[i][jn][3] + bb.y);
#pragma unroll
            for (int u = 0; u < 2; u++) {
                const int m = mlo + u * 8;
                const float2 v = (u == 0) ? v0 : v1;
                if (MODE == 0) {
                    *(float2*)&out[(size_t)m * Dv + nb] = v;
                } else if (MODE == 1) {
                    int b = m >> 11, t = m & 2047;
                    int h = nb >> 6, hd = nb & 63;
                    *(float2*)&out[((size_t)(b * Hv + h) * Tv + t) * 80 + hd] = v;
                } else if (MODE == 2) {
                    int b = m >> 11, t = m & 2047;
                    int h = nb >> 6, hd = nb & 63;
                    size_t vt = ((size_t)((b * Hv + h) * HDv + hd)) * Tv + t;
                    out[vt] = __uint_as_float(tf32_hif(v.x));
                    out[vt + Tv] = __uint_as_float(tf32_hif(v.y));
                    *(float2*)&out2[(((size_t)(b * Hv + h) * Tv) + t) * HDv + hd] = v;
                } else {  // MODE 3: K hi/lo
                    int b = m >> 11, t = m & 2047;
                    int h = nb >> 6, hd = nb & 63;
                    size_t idx = ((size_t)(b * Hv + h) * Tv + t) * 80 + hd;
                    uint32_t hx = tf32_hif(v.x), hy = tf32_hif(v.y);
                    float lx = v.x - __uint_as_float(hx), ly = v.y - __uint_as_float(hy);
                    *(float2*)&out[idx] = make_float2(__uint_as_float(hx), __uint_as_float(hy));
                    *(float2*)&out2[idx] = make_float2(__uint_as_float(tf32_hif(lx)),
                                                       __uint_as_float(tf32_hif(ly)));
                }
            }
        }
    }
}

// ---------------------------------------------------------------------------
// STP: per (b,h,t) row, compute q_stp[3] and cross(k3, v3)[3]; write q_stp to
// g_Qe cols 64-71, cross_kv (tf32 hi/lo) to g_KeH/g_KeL cols 64-71.
// ---------------------------------------------------------------------------
__global__ __launch_bounds__(256) void stp_kernel(const float* __restrict__ Wqs,
                                                  const float* __restrict__ bqs,
                                                  const float* __restrict__ Wks,
                                                  const float* __restrict__ bks,
                                                  const float* __restrict__ Wvs,
                                                  const float* __restrict__ bvs) {
    int warp = (blockIdx.x * blockDim.x + threadIdx.x) >> 5;
    int lane = threadIdx.x & 31;
    if (warp >= Bv * Hv * Tv) return;

    const float* q = g_Qe + (size_t)warp * 80;
    const float* kh = g_KeH + (size_t)warp * 80;
    const float* kl = g_KeL + (size_t)warp * 80;
    const float* v = g_V + (size_t)warp * HDv;

    float q0 = q[lane], q1 = q[lane + 32];
    float k0 = kh[lane] + kl[lane], k1 = kh[lane + 32] + kl[lane + 32];
    float v0 = v[lane], v1 = v[lane + 32];

    float qs[3], k3[3], v3[3];
#pragma unroll
    for (int c = 0; c < 3; c++) {
        float pq = q0 * Wqs[c * HDv + lane] + q1 * Wqs[c * HDv + lane + 32];
        float pk = k0 * Wks[c * HDv + lane] + k1 * Wks[c * HDv + lane + 32];
        float pv = v0 * Wvs[c * HDv + lane] + v1 * Wvs[c * HDv + lane + 32];
#pragma unroll
        for (int o = 16; o > 0; o >>= 1) {
            pq += __shfl_xor_sync(0xffffffffu, pq, o);
            pk += __shfl_xor_sync(0xffffffffu, pk, o);
            pv += __shfl_xor_sync(0xffffffffu, pv, o);
        }
        qs[c] = pq + bqs[c];
        k3[c] = pk + bks[c];
        v3[c] = pv + bvs[c];
    }

    if (lane == 0) {
        float4* qe = (float4*)(g_Qe + (size_t)warp * 80 + 64);
        qe[0] = make_float4(qs[0], qs[1], qs[2], 0.f);
        qe[1] = make_float4(0.f, 0.f, 0.f, 0.f);
        float c0 = k3[1] * v3[2] - k3[2] * v3[1];
        float c1 = k3[2] * v3[0] - k3[0] * v3[2];
        float c2 = k3[0] * v3[1] - k3[1] * v3[0];
        uint32_t h0 = tf32_hif(c0), h1 = tf32_hif(c1), h2 = tf32_hif(c2);
        float4* keh = (float4*)(g_KeH + (size_t)warp * 80 + 64);
        keh[0] = make_float4(__uint_as_float(h0), __uint_as_float(h1), __uint_as_float(h2), 0.f);
        keh[1] = make_float4(0.f, 0.f, 0.f, 0.f);
        float4* kel = (float4*)(g_KeL + (size_t)warp * 80 + 64);
        kel[0] = make_float4(__uint_as_float(tf32_hif(c0 - __uint_as_float(h0))),
                             __uint_as_float(tf32_hif(c1 - __uint_as_float(h1))),
                             __uint_as_float(tf32_hif(c2 - __uint_as_float(h2))), 0.f);
        kel[1] = make_float4(0.f, 0.f, 0.f, 0.f);
    }
}

// ---------------------------------------------------------------------------
// mma.sync flash attention, split-free hot loop. CTA = 128 q-rows; 8 warps.
// K hi/lo precomputed -> one ldsm4 fetches {bh0,bh1,bl0,bl1} (lanes 0-15 hi,
// lanes 16-31 lo). V pre-rounded tf32 -> PV consumes raw bits.
// Smem: Khi [0,43008), Klo [43008,86016), V [86016,120832), P [120832,155648).
// ---------------------------------------------------------------------------
#define QPB 336   // Q/K smem pitch bytes (84 floats; 336 % 128 = 80 -> conflict-free)
#define VPB 272   // V/P smem pitch bytes (68 floats; 272 % 128 = 16 -> conflict-free)
#define KLO_OFF 43008u
#define V_OFF 86016u
#define P_OFF 120832u
#define ATT_SMEM 155648

__global__ __launch_bounds__(256, 1) void attn_mma(const float* __restrict__ temp_p) {
    extern __shared__ char dsm[];
    const uint32_t base = smem_u32(dsm);
    const int b = blockIdx.z, h = blockIdx.y;
    const int q0 = blockIdx.x * 128;
    const int tid = threadIdx.x, lane = tid & 31, wid = tid >> 5;
    const float temp = *temp_p;

    const float* Qe = g_Qe + ((size_t)(b * Hv + h) * Tv + q0) * 80;
    const float* KeH = g_KeH + (size_t)(b * Hv + h) * Tv * 80;
    const float* KeL = g_KeL + (size_t)(b * Hv + h) * Tv * 80;
    const float* Vt = g_Vt + (size_t)(b * Hv + h) * HDv * Tv;

    // ---- stage Q (borrow Khi region), split to registers ----
#pragma unroll
    for (int i = 0; i < 10; i++) {
        int idx = tid + i * 256;
        int row = idx / 20, c = idx % 20;
        cp16(base + (uint32_t)row * QPB + c * 16, Qe + row * 80 + c * 4);
    }
    cp_commit();
    cp_wait<0>();
    __syncthreads();

    uint32_t qh[9][4], ql[9][4];
    {
        const uint32_t qa = base + (uint32_t)(wid * 16) * QPB +
            ((lane & 7) + ((lane >> 3) & 1) * 8) * QPB + ((lane >> 4) & 1) * 16;
#pragma unroll
        for (int ka = 0; ka < 9; ka++) {
            uint32_t r0, r1, r2, r3;
            ldsm4(r0, r1, r2, r3, qa + ka * 32);
            split_tf32(r0, qh[ka][0], ql[ka][0]);
            split_tf32(r1, qh[ka][1], ql[ka][1]);
            split_tf32(r2, qh[ka][2], ql[ka][2]);
            split_tf32(r3, qh[ka][3], ql[ka][3]);
        }
    }
    __syncthreads();   // Q staging area free before K loads

    float of[8][4];
#pragma unroll
    for (int j = 0; j < 8; j++)
#pragma unroll
        for (int r = 0; r < 4; r++) of[j][r] = 0.0f;
    float m0 = -INFINITY, m1 = -INFINITY, l0 = 0.f, l1 = 0.f;

    auto load_tile = [&](int kt, int s) {
        uint32_t kb = base + (uint32_t)s * 21504u;
#pragma unroll
        for (int i = 0; i < 5; i++) {
            int idx = tid + i * 256;
            int row = idx / 20, c = idx % 20;
            cp16(kb + (uint32_t)row * QPB + c * 16, KeH + (size_t)(kt * 64 + row) * 80 + c * 4);
            cp16(kb + KLO_OFF + (uint32_t)row * QPB + c * 16, KeL + (size_t)(kt * 64 + row) * 80 + c * 4);
        }
        uint32_t vb = base + V_OFF + (uint32_t)s * 17408u;
#pragma unroll
        for (int i = 0; i < 4; i++) {
            int idx = tid + i * 256;
            int row = idx >> 4, c = idx & 15;
            cp16(vb + (uint32_t)row * VPB + c * 16, Vt + (size_t)row * Tv + kt * 64 + c * 4);
        }
        cp_commit();
    };

    load_tile(0, 0);
    load_tile(1, 1);

    const uint32_t pw = base + P_OFF + (uint32_t)wid * 4352u;
    const uint32_t offAP = ((lane & 7) + ((lane >> 3) & 1) * 8) * VPB + ((lane >> 4) & 1) * 16;
    // K fragment per-lane offset: lanes 0-15 hi tile, 16-31 lo tile
    const uint32_t kfrag = ((lane >> 4) & 1) * KLO_OFF + (lane & 7) * QPB + ((lane >> 3) & 1) * 16;
    const int rquad = lane >> 2, qq = lane & 3;

    for (int kt = 0; kt < 32; kt++) {
        cp_wait<1>();
        __syncthreads();
        const int s = kt & 1;
        const uint32_t kb = base + (uint32_t)s * 21504u + kfrag;
        const uint32_t vb = base + V_OFF + (uint32_t)s * 17408u;

        // ---- scores (3xTF32, split-free: hi/lo fetched together) ----
        float sf[8][4];
#pragma unroll
        for (int j = 0; j < 8; j++)
#pragma unroll
            for (int r = 0; r < 4; r++) sf[j][r] = 0.0f;

#pragma unroll
        for (int jn = 0; jn < 8; jn++) {
            const uint32_t baddr = kb + (uint32_t)(jn * 8) * QPB;
#pragma unroll
            for (int ka = 0; ka < 9; ka++) {
                uint32_t bh0, bh1, bl0, bl1;
                ldsm4(bh0, bh1, bl0, bl1, baddr + ka * 32);
                mma_tf32(sf[jn], qh[ka], bh0, bh1);
                mma_tf32(sf[jn], qh[ka], bl0, bl1);
                mma_tf32(sf[jn], ql[ka], bh0, bh1);
            }
        }

        // ---- online softmax ----
        float tmax0 = -INFINITY, tmax1 = -INFINITY;
#pragma unroll
        for (int j = 0; j < 8; j++) {
            sf[j][0] *= temp; sf[j][1] *= temp; sf[j][2] *= temp; sf[j][3] *= temp;
            tmax0 = fmaxf(tmax0, fmaxf(sf[j][0], sf[j][1]));
            tmax1 = fmaxf(tmax1, fmaxf(sf[j][2], sf[j][3]));
        }
        tmax0 = fmaxf(tmax0, __shfl_xor_sync(0xffffffffu, tmax0, 1));
        tmax0 = fmaxf(tmax0, __shfl_xor_sync(0xffffffffu, tmax0, 2));
        tmax1 = fmaxf(tmax1, __shfl_xor_sync(0xffffffffu, tmax1, 1));
        tmax1 = fmaxf(tmax1, __shfl_xor_sync(0xffffffffu, tmax1, 2));

        const float mn0 = fmaxf(m0, tmax0), mn1 = fmaxf(m1, tmax1);
        const float sc0 = __expf(m0 - mn0), sc1 = __expf(m1 - mn1);
        m0 = mn0; m1 = mn1;

        float ts0 = 0.f, ts1 = 0.f;
#pragma unroll
        for (int j = 0; j < 8; j++) {
            sf[j][0] = __expf(sf[j][0] - mn0);
            sf[j][1] = __expf(sf[j][1] - mn0);
            sf[j][2] = __expf(sf[j][2] - mn1);
            sf[j][3] = __expf(sf[j][3] - mn1);
            ts0 += sf[j][0] + sf[j][1];
            ts1 += sf[j][2] + sf[j][3];
        }
        ts0 += __shfl_xor_sync(0xffffffffu, ts0, 1);
        ts0 += __shfl_xor_sync(0xffffffffu, ts0, 2);
        ts1 += __shfl_xor_sync(0xffffffffu, ts1, 1);
        ts1 += __shfl_xor_sync(0xffffffffu, ts1, 2);
        l0 = l0 * sc0 + ts0;
        l1 = l1 * sc1 + ts1;

#pragma unroll
        for (int j = 0; j < 8; j++) {
            of[j][0] *= sc0; of[j][1] *= sc0; of[j][2] *= sc1; of[j][3] *= sc1;
        }

        // ---- P to per-warp smem, re-enter as A operand ----
#pragma unroll
        for (int j = 0; j < 8; j++) {
            uint32_t col = (uint32_t)(j * 8 + 2 * qq) * 4;
            sts64(pw + (uint32_t)rquad * VPB + col, sf[j][0], sf[j][1]);
            sts64(pw + (uint32_t)(rquad + 8) * VPB + col, sf[j][2], sf[j][3]);
        }
        __syncwarp();

        // ---- PV (single-pass tf32; V pre-rounded) ----
#pragma unroll
        for (int ka = 0; ka < 8; ka++) {
            uint32_t r0, r1, r2, r3;
            ldsm4(r0, r1, r2, r3, pw + offAP + ka * 32);
            uint32_t ph[4];
            ph[0] = tf32_hi(r0);
            ph[1] = tf32_hi(r1);
            ph[2] = tf32_hi(r2);
            ph[3] = tf32_hi(r3);
#pragma unroll
            for (int jn = 0; jn < 8; jn++) {
                uint32_t v0, v1;
                ldsm2(v0, v1, vb + (uint32_t)(jn * 8 + (lane & 7)) * VPB + ((lane >> 3) & 1) * 16 + ka * 32);
                mma_tf32(of[jn], ph, v0, v1);
            }
        }

        __syncthreads();   // stage s fully consumed before refill
        const int nxt = kt + 2;
        if (nxt < 32) load_tile(nxt, s);
        else cp_commit();
    }

    // ---- epilogue ----
    const float inv0 = 1.0f / l0, inv1 = 1.0f / l1;
    const int t0 = q0 + wid * 16 + rquad;
#pragma unroll
    for (int j = 0; j < 8; j++) {
        const int col = h * 64 + j * 8 + 2 * qq;
        *(float2*)&g_AO[(size_t)(b * Tv + t0) * Dv + col] =
            make_float2(of[j][0] * inv0, of[j][1] * inv0);
        *(float2*)&g_AO[(size_t)(b * Tv + t0 + 8) * Dv + col] =
            make_float2(of[j][2] * inv1, of[j][3] * inv1);
    }
}

// ---------------------------------------------------------------------------
extern "C" void kernel_launch(void* const* d_in, const int* in_sizes, int n_in,
                              void* d_out, int out_size) {
    const float* x   = (const float*)d_in[0];
    const float* Wq  = (const float*)d_in[1];
    const float* bq  = (const float*)d_in[2];
    const float* Wk  = (const float*)d_in[3];
    const float* bk  = (const float*)d_in[4];
    const float* Wv  = (const float*)d_in[5];
    const float* bv  = (const float*)d_in[6];
    const float* Wo  = (const float*)d_in[7];
    const float* bo  = (const float*)d_in[8];
    const float* Wqs = (const float*)d_in[9];
    const float* bqs = (const float*)d_in[10];
    const float* Wks = (const float*)d_in[11];
    const float* bks = (const float*)d_in[12];
    const float* Wvs = (const float*)d_in[13];
    const float* bvs = (const float*)d_in[14];
    const float* temp = (const float*)d_in[15];

    float *gQe, *gKeH, *gKeL, *gV, *gVt, *gAO;
    cudaGetSymbolAddress((void**)&gQe, g_Qe);
    cudaGetSymbolAddress((void**)&gKeH, g_KeH);
    cudaGetSymbolAddress((void**)&gKeL, g_KeL);
    cudaGetSymbolAddress((void**)&gV, g_V);
    cudaGetSymbolAddress((void**)&gVt, g_Vt);
    cudaGetSymbolAddress((void**)&gAO, g_AO);

    const int dyn_smem = 4 * STAGE_BYTES;   // 73728
    cudaFuncSetAttribute(gemm_mma<0>, cudaFuncAttributeMaxDynamicSharedMemorySize, dyn_smem);
    cudaFuncSetAttribute(gemm_mma<1>, cudaFuncAttributeMaxDynamicSharedMemorySize, dyn_smem);
    cudaFuncSetAttribute(gemm_mma<2>, cudaFuncAttributeMaxDynamicSharedMemorySize, dyn_smem);
    cudaFuncSetAttribute(gemm_mma<3>, cudaFuncAttributeMaxDynamicSharedMemorySize, dyn_smem);
    cudaFuncSetAttribute(attn_mma, cudaFuncAttributeMaxDynamicSharedMemorySize, ATT_SMEM);

    dim3 ggrid(Dv / 128, Mv / 128);   // (8, 32)
    gemm_mma<1><<<ggrid, 256, dyn_smem>>>(x, Wq, bq, gQe, nullptr);
    gemm_mma<3><<<ggrid, 256, dyn_smem>>>(x, Wk, bk, gKeH, gKeL);
    gemm_mma<2><<<ggrid, 256, dyn_smem>>>(x, Wv, bv, gVt, gV);

    int nwarps = Bv * Hv * Tv;                 // 65536
    stp_kernel<<<nwarps / 8, 256>>>(Wqs, bqs, Wks, bks, Wvs, bvs);

    dim3 agrid(Tv / 128, Hv, Bv);              // (16, 16, 2)
    attn_mma<<<agrid, 256, ATT_SMEM>>>(temp);

    gemm_mma<0><<<ggrid, 256, dyn_smem>>>(gAO, Wo, bo, (float*)d_out, nullptr);
}

// round 11
// speedup vs baseline: 3.4188x; 1.1112x over previous
#include <cuda_runtime.h>
#include <cuda_bf16.h>
#include <math.h>
#include <stdint.h>

#define Bv 2
#define Tv 2048
#define Dv 1024
#define Hv 16
#define HDv 64
#define Mv (Bv * Tv)   // 4096

// Scratch (allocation-free rule: __device__ globals; zero-initialized at load)
__device__ __nv_bfloat16 g_QeH[Bv * Hv * Tv * 80];  // bf16-hi of q / q_stp (cols 64-66)
__device__ __nv_bfloat16 g_QeL[Bv * Hv * Tv * 80];  // bf16-lo residual
__device__ __nv_bfloat16 g_KeH[Bv * Hv * Tv * 80];  // bf16-hi of k / cross_kv
__device__ __nv_bfloat16 g_KeL[Bv * Hv * Tv * 80];  // bf16-lo residual
__device__ float g_V  [Bv * Hv * Tv * HDv]; // [b,h,t,hd] full precision (for stp)
__device__ float g_Vt [Bv * Hv * HDv * Tv]; // [b,h,hd,t] tf32-rounded (for PV mma)
__device__ float g_AO [Bv * Tv * Dv];       // attention out, [b,t,h*HD+hd]

// ======================= base-ISA helpers (sm_80-class) =====================
__device__ __forceinline__ uint32_t smem_u32(const void* p) {
    uint32_t a;
    asm("{ .reg .u64 t; cvta.to.shared.u64 t, %1; cvt.u32.u64 %0, t; }" : "=r"(a) : "l"(p));
    return a;
}
__device__ __forceinline__ void cp16(uint32_t dst, const void* src) {
    asm volatile("cp.async.cg.shared.global [%0], [%1], 16;" :: "r"(dst), "l"(src) : "memory");
}
__device__ __forceinline__ void cp_commit() {
    asm volatile("cp.async.commit_group;" ::: "memory");
}
template <int N>
__device__ __forceinline__ void cp_wait() {
    asm volatile("cp.async.wait_group %0;" :: "n"(N) : "memory");
}
__device__ __forceinline__ void ldsm4(uint32_t& r0, uint32_t& r1, uint32_t& r2, uint32_t& r3,
                                      uint32_t addr) {
    asm volatile("ldmatrix.sync.aligned.m8n8.x4.shared.b16 {%0,%1,%2,%3}, [%4];"
                 : "=r"(r0), "=r"(r1), "=r"(r2), "=r"(r3) : "r"(addr));
}
__device__ __forceinline__ void ldsm2(uint32_t& r0, uint32_t& r1, uint32_t addr) {
    asm volatile("ldmatrix.sync.aligned.m8n8.x2.shared.b16 {%0,%1}, [%2];"
                 : "=r"(r0), "=r"(r1) : "r"(addr));
}
__device__ __forceinline__ void sts64(uint32_t addr, float x, float y) {
    asm volatile("st.shared.v2.f32 [%0], {%1,%2};" :: "r"(addr), "f"(x), "f"(y) : "memory");
}
__device__ __forceinline__ void mma_tf32(float* d, const uint32_t* a, uint32_t b0, uint32_t b1) {
    asm volatile(
        "mma.sync.aligned.m16n8k8.row.col.f32.tf32.tf32.f32 "
        "{%0,%1,%2,%3}, {%4,%5,%6,%7}, {%8,%9}, {%0,%1,%2,%3};"
        : "+f"(d[0]), "+f"(d[1]), "+f"(d[2]), "+f"(d[3])
        : "r"(a[0]), "r"(a[1]), "r"(a[2]), "r"(a[3]), "r"(b0), "r"(b1));
}
__device__ __forceinline__ void mma_bf16(float* d, const uint32_t* a, uint32_t b0, uint32_t b1) {
    asm volatile(
        "mma.sync.aligned.m16n8k16.row.col.f32.bf16.bf16.f32 "
        "{%0,%1,%2,%3}, {%4,%5,%6,%7}, {%8,%9}, {%0,%1,%2,%3};"
        : "+f"(d[0]), "+f"(d[1]), "+f"(d[2]), "+f"(d[3])
        : "r"(a[0]), "r"(a[1]), "r"(a[2]), "r"(a[3]), "r"(b0), "r"(b1));
}
// 3xTF32 split: hi = tf32(x), lo = tf32(x - hi)
__device__ __forceinline__ void split_tf32(uint32_t raw, uint32_t& hi, uint32_t& lo) {
    float f = __uint_as_float(raw);
    asm("cvt.rna.tf32.f32 %0, %1;" : "=r"(hi) : "f"(f));
    float r = f - __uint_as_float(hi);
    asm("cvt.rna.tf32.f32 %0, %1;" : "=r"(lo) : "f"(r));
}
__device__ __forceinline__ uint32_t tf32_hi(uint32_t raw) {
    uint32_t hi;
    asm("cvt.rna.tf32.f32 %0, %1;" : "=r"(hi) : "f"(__uint_as_float(raw)));
    return hi;
}
__device__ __forceinline__ uint32_t tf32_hif(float f) {
    uint32_t hi;
    asm("cvt.rna.tf32.f32 %0, %1;" : "=r"(hi) : "f"(f));
    return hi;
}
// bf16 hi/lo split of an fp32
__device__ __forceinline__ void split_bf16(float f, __nv_bfloat16& h, __nv_bfloat16& l) {
    h = __float2bfloat16_rn(f);
    l = __float2bfloat16_rn(f - __bfloat162float(h));
}

// ---------------------------------------------------------------------------
// 3xTF32 mma.sync GEMM: C[m,n] = sum_k X[m,k] * W[n,k] + bias[n]
// MODE 0: plain row-major. MODE 1: Q head-split pitch-80 bf16 hi/lo planes.
// MODE 2: V dual-write (g_Vt transposed tf32-rounded, g_V full head-split).
// MODE 3: K head-split pitch-80 bf16 hi/lo planes.
// ---------------------------------------------------------------------------
#define PITCH 36
#define PITCHB (PITCH * 4)           // 144 bytes
#define STAGE_BYTES (128 * PITCHB)   // 18432
#define KCH 32
#define NSTEP (1024 / KCH)           // 32

template <int MODE>
__global__ __launch_bounds__(256) void gemm_mma(const float* __restrict__ X,
                                                const float* __restrict__ W,
                                                const float* __restrict__ bias,
                                                float* __restrict__ out,
                                                float* __restrict__ out2) {
    extern __shared__ char dsm[];
    const uint32_t sbase = smem_u32(dsm);
    const int K = 1024;
    const int n0 = blockIdx.x * 128;
    const int m0 = blockIdx.y * 128;
    const int tid = threadIdx.x;
    const int lane = tid & 31;
    const int wid = tid >> 5;
    const int wm = wid >> 2;
    const int wn = wid & 3;

    uint32_t Ab[2], Wb[2];
    Ab[0] = sbase;                     Wb[0] = sbase + STAGE_BYTES;
    Ab[1] = sbase + 2 * STAGE_BYTES;   Wb[1] = sbase + 3 * STAGE_BYTES;

    const uint32_t offA = ((lane & 7) + ((lane >> 3) & 1) * 8) * PITCHB + ((lane >> 4) & 1) * 16;
    const uint32_t offB = (lane & 7) * PITCHB + ((lane >> 3) & 1) * 16;
    const uint32_t aWarp = (uint32_t)(wm * 64) * PITCHB + offA;
    const uint32_t bWarp = (uint32_t)(wn * 32) * PITCHB + offB;

    const int lrow0 = tid >> 3;
    const int lc4 = (tid & 7) * 16;

    float acc[4][4][4];
#pragma unroll
    for (int i = 0; i < 4; i++)
#pragma unroll
        for (int j = 0; j < 4; j++)
#pragma unroll
            for (int r = 0; r < 4; r++) acc[i][j][r] = 0.0f;

#pragma unroll
    for (int s = 0; s < 2; s++) {
        const int k0 = s * KCH;
#pragma unroll
        for (int it = 0; it < 4; it++) {
            int row = lrow0 + it * 32;
            cp16(Ab[s] + (uint32_t)row * PITCHB + lc4, &X[(size_t)(m0 + row) * K + k0] + (lc4 >> 2));
            cp16(Wb[s] + (uint32_t)row * PITCHB + lc4, &W[(size_t)(n0 + row) * K + k0] + (lc4 >> 2));
        }
        cp_commit();
    }

    for (int c = 0; c < NSTEP; c++) {
        cp_wait<1>();
        __syncthreads();
        const int s = c & 1;
        const uint32_t Abase = Ab[s] + aWarp;
        const uint32_t Bbase = Wb[s] + bWarp;

#pragma unroll
        for (int ka = 0; ka < 4; ka++) {
            uint32_t bh0[4], bh1[4], bl0[4], bl1[4];
#pragma unroll
            for (int jn = 0; jn < 4; jn++) {
                uint32_t r0, r1;
                ldsm2(r0, r1, Bbase + (uint32_t)(jn * 8) * PITCHB + ka * 32);
                split_tf32(r0, bh0[jn], bl0[jn]);
                split_tf32(r1, bh1[jn], bl1[jn]);
            }
#pragma unroll
            for (int i = 0; i < 4; i++) {
                uint32_t r0, r1, r2, r3;
                ldsm4(r0, r1, r2, r3, Abase + (uint32_t)(i * 16) * PITCHB + ka * 32);
                uint32_t ah[4], al[4];
                split_tf32(r0, ah[0], al[0]);
                split_tf32(r1, ah[1], al[1]);
                split_tf32(r2, ah[2], al[2]);
                split_tf32(r3, ah[3], al[3]);
#pragma unroll
                for (int jn = 0; jn < 4; jn++) {
                    mma_tf32(acc[i][jn], ah, bh0[jn], bh1[jn]);
                    mma_tf32(acc[i][jn], ah, bl0[jn], bl1[jn]);
                    mma_tf32(acc[i][jn], al, bh0[jn], bh1[jn]);
                }
            }
        }
        __syncthreads();

        const int nxt = c + 2;
        if (nxt < NSTEP) {
            const int k0 = nxt * KCH;
#pragma unroll
            for (int it = 0; it < 4; it++) {
                int row = lrow0 + it * 32;
                cp16(Ab[s] + (uint32_t)row * PITCHB + lc4, &X[(size_t)(m0 + row) * K + k0] + (lc4 >> 2));
                cp16(Wb[s] + (uint32_t)row * PITCHB + lc4, &W[(size_t)(n0 + row) * K + k0] + (lc4 >> 2));
            }
        }
        cp_commit();
    }

#pragma unroll
    for (int i = 0; i < 4; i++) {
        const int mlo = m0 + wm * 64 + i * 16 + (lane >> 2);
#pragma unroll
        for (int jn = 0; jn < 4; jn++) {
            const int nb = n0 + wn * 32 + jn * 8 + (lane & 3) * 2;
            const float2 bb = *(const float2*)&bias[nb];
            float2 v0 = make_float2(acc[i][jn][0] + bb.x, acc[i][jn][1] + bb.y);
            float2 v1 = make_float2(acc[i][jn][2] + bb.x, acc[i][jn][3] + bb.y);
#pragma unroll
            for (int u = 0; u < 2; u++) {
                const int m = mlo + u * 8;
                const float2 v = (u == 0) ? v0 : v1;
                if (MODE == 0) {
                    *(float2*)&out[(size_t)m * Dv + nb] = v;
                } else if (MODE == 1 || MODE == 3) {
                    // bf16 hi/lo planes, pitch 80
                    int b = m >> 11, t = m & 2047;
                    int h = nb >> 6, hd = nb & 63;
                    size_t idx = ((size_t)(b * Hv + h) * Tv + t) * 80 + hd;
                    __nv_bfloat16 hx, lx, hy, ly;
                    split_bf16(v.x, hx, lx);
                    split_bf16(v.y, hy, ly);
                    __nv_bfloat16* oh = (__nv_bfloat16*)out;
                    __nv_bfloat16* ol = (__nv_bfloat16*)out2;
                    *(__nv_bfloat162*)&oh[idx] = __nv_bfloat162(hx, hy);
                    *(__nv_bfloat162*)&ol[idx] = __nv_bfloat162(lx, ly);
                } else {  // MODE 2: V dual-write
                    int b = m >> 11, t = m & 2047;
                    int h = nb >> 6, hd = nb & 63;
                    size_t vt = ((size_t)((b * Hv + h) * HDv + hd)) * Tv + t;
                    out[vt] = __uint_as_float(tf32_hif(v.x));
                    out[vt + Tv] = __uint_as_float(tf32_hif(v.y));
                    *(float2*)&out2[(((size_t)(b * Hv + h) * Tv) + t) * HDv + hd] = v;
                }
            }
        }
    }
}

// ---------------------------------------------------------------------------
// STP: per (b,h,t) row, compute q_stp[3] and cross(k3, v3)[3]; write bf16
// hi/lo into cols 64-71 of the Q / K planes.
// ---------------------------------------------------------------------------
__global__ __launch_bounds__(256) void stp_kernel(const float* __restrict__ Wqs,
                                                  const float* __restrict__ bqs,
                                                  const float* __restrict__ Wks,
                                                  const float* __restrict__ bks,
                                                  const float* __restrict__ Wvs,
                                                  const float* __restrict__ bvs) {
    int warp = (blockIdx.x * blockDim.x + threadIdx.x) >> 5;
    int lane = threadIdx.x & 31;
    if (warp >= Bv * Hv * Tv) return;

    const __nv_bfloat16* qh = g_QeH + (size_t)warp * 80;
    const __nv_bfloat16* ql = g_QeL + (size_t)warp * 80;
    const __nv_bfloat16* kh = g_KeH + (size_t)warp * 80;
    const __nv_bfloat16* kl = g_KeL + (size_t)warp * 80;
    const float* v = g_V + (size_t)warp * HDv;

    float q0 = __bfloat162float(qh[lane]) + __bfloat162float(ql[lane]);
    float q1 = __bfloat162float(qh[lane + 32]) + __bfloat162float(ql[lane + 32]);
    float k0 = __bfloat162float(kh[lane]) + __bfloat162float(kl[lane]);
    float k1 = __bfloat162float(kh[lane + 32]) + __bfloat162float(kl[lane + 32]);
    float v0 = v[lane], v1 = v[lane + 32];

    float qs[3], k3[3], v3[3];
#pragma unroll
    for (int c = 0; c < 3; c++) {
        float pq = q0 * Wqs[c * HDv + lane] + q1 * Wqs[c * HDv + lane + 32];
        float pk = k0 * Wks[c * HDv + lane] + k1 * Wks[c * HDv + lane + 32];
        float pv = v0 * Wvs[c * HDv + lane] + v1 * Wvs[c * HDv + lane + 32];
#pragma unroll
        for (int o = 16; o > 0; o >>= 1) {
            pq += __shfl_xor_sync(0xffffffffu, pq, o);
            pk += __shfl_xor_sync(0xffffffffu, pk, o);
            pv += __shfl_xor_sync(0xffffffffu, pv, o);
        }
        qs[c] = pq + bqs[c];
        k3[c] = pk + bks[c];
        v3[c] = pv + bvs[c];
    }

    if (lane == 0) {
        float cr[3];
        cr[0] = k3[1] * v3[2] - k3[2] * v3[1];
        cr[1] = k3[2] * v3[0] - k3[0] * v3[2];
        cr[2] = k3[0] * v3[1] - k3[1] * v3[0];
        __nv_bfloat16 z = __float2bfloat16_rn(0.f);
        __nv_bfloat16 qhv[8], qlv[8], khv[8], klv[8];
#pragma unroll
        for (int c = 0; c < 8; c++) { qhv[c] = z; qlv[c] = z; khv[c] = z; klv[c] = z; }
#pragma unroll
        for (int c = 0; c < 3; c++) {
            split_bf16(qs[c], qhv[c], qlv[c]);
            split_bf16(cr[c], khv[c], klv[c]);
        }
        *(float4*)&g_QeH[(size_t)warp * 80 + 64] = *(float4*)qhv;
        *(float4*)&g_QeL[(size_t)warp * 80 + 64] = *(float4*)qlv;
        *(float4*)&g_KeH[(size_t)warp * 80 + 64] = *(float4*)khv;
        *(float4*)&g_KeL[(size_t)warp * 80 + 64] = *(float4*)klv;
    }
}

// ---------------------------------------------------------------------------
// mma.sync flash attention. CTA = 128 q-rows of one head; 8 warps x 16 rows.
// Scores: bf16x3 m16n8k16 over 80 dims (5 atoms), K hi/lo via lane-mapped
// ldsm4, Q hi/lo in registers. PV: single-pass tf32 (V pre-rounded).
// Smem: K stages [0, 45056) (hi at +0, lo at +11264 per 22528-stage),
//       V [45056, 79872), P [79872, 114688).
// ---------------------------------------------------------------------------
#define KPB 176   // K/Q bf16 smem pitch bytes (11x16B; 11 mod 8 coprime -> conflict-free)
#define VPB 272   // V/P smem pitch bytes (68 floats; 272 % 128 = 16 -> conflict-free)
#define KSTAGE 22528u
#define KLO_OFF 11264u
#define V_OFF 45056u
#define P_OFF 79872u
#define ATT_SMEM 114688

__global__ __launch_bounds__(256, 1) void attn_mma(const float* __restrict__ temp_p) {
    extern __shared__ char dsm[];
    const uint32_t base = smem_u32(dsm);
    const int b = blockIdx.z, h = blockIdx.y;
    const int q0 = blockIdx.x * 128;
    const int tid = threadIdx.x, lane = tid & 31, wid = tid >> 5;
    const float temp = *temp_p;

    const __nv_bfloat16* QeH = g_QeH + ((size_t)(b * Hv + h) * Tv + q0) * 80;
    const __nv_bfloat16* QeL = g_QeL + ((size_t)(b * Hv + h) * Tv + q0) * 80;
    const __nv_bfloat16* KeH = g_KeH + (size_t)(b * Hv + h) * Tv * 80;
    const __nv_bfloat16* KeL = g_KeL + (size_t)(b * Hv + h) * Tv * 80;
    const float* Vt = g_Vt + (size_t)(b * Hv + h) * HDv * Tv;

    // ---- stage Q hi/lo (borrow K region: hi at base, lo at base+22528) ----
#pragma unroll
    for (int i = 0; i < 10; i++) {
        int idx = tid + i * 256;          // 0..2559
        int plane = idx >= 1280;
        int rem = idx - plane * 1280;
        int row = rem / 10, c = rem % 10;
        const __nv_bfloat16* src = plane ? QeL : QeH;
        cp16(base + (uint32_t)plane * KSTAGE + (uint32_t)row * KPB + c * 16,
             src + (size_t)row * 80 + c * 8);
    }
    cp_commit();
    cp_wait<0>();
    __syncthreads();

    uint32_t qh[5][4], ql[5][4];
    {
        const uint32_t qa = base + (uint32_t)(wid * 16) * KPB +
            ((lane & 7) + ((lane >> 3) & 1) * 8) * KPB + ((lane >> 4) & 1) * 16;
#pragma unroll
        for (int ka = 0; ka < 5; ka++) {
            ldsm4(qh[ka][0], qh[ka][1], qh[ka][2], qh[ka][3], qa + ka * 32);
            ldsm4(ql[ka][0], ql[ka][1], ql[ka][2], ql[ka][3], qa + KSTAGE + ka * 32);
        }
    }
    __syncthreads();   // Q staging area free before K loads

    float of[8][4];
#pragma unroll
    for (int j = 0; j < 8; j++)
#pragma unroll
        for (int r = 0; r < 4; r++) of[j][r] = 0.0f;
    float m0 = -INFINITY, m1 = -INFINITY, l0 = 0.f, l1 = 0.f;

    auto load_tile = [&](int kt, int s) {
        uint32_t kb = base + (uint32_t)s * KSTAGE;
#pragma unroll
        for (int i = 0; i < 5; i++) {
            int idx = tid + i * 256;       // 0..1279
            int plane = idx >= 640;
            int rem = idx - plane * 640;
            int row = rem / 10, c = rem % 10;
            const __nv_bfloat16* src = plane ? KeL : KeH;
            cp16(kb + (uint32_t)plane * KLO_OFF + (uint32_t)row * KPB + c * 16,
                 src + (size_t)(kt * 64 + row) * 80 + c * 8);
        }
        uint32_t vb = base + V_OFF + (uint32_t)s * 17408u;
#pragma unroll
        for (int i = 0; i < 4; i++) {
            int idx = tid + i * 256;
            int row = idx >> 4, c = idx & 15;
            cp16(vb + (uint32_t)row * VPB + c * 16, Vt + (size_t)row * Tv + kt * 64 + c * 4);
        }
        cp_commit();
    };

    load_tile(0, 0);
    load_tile(1, 1);

    const uint32_t pw = base + P_OFF + (uint32_t)wid * 4352u;
    const uint32_t offAP = ((lane & 7) + ((lane >> 3) & 1) * 8) * VPB + ((lane >> 4) & 1) * 16;
    // K fragment per-lane offset: lanes 0-15 hi plane, 16-31 lo plane;
    // within plane: row = jn*8 + (lane&7), 16B chunk = ((lane>>3)&1).
    const uint32_t kfrag = ((lane >> 4) & 1) * KLO_OFF + (lane & 7) * KPB + ((lane >> 3) & 1) * 16;
    const int rquad = lane >> 2, qq = lane & 3;

    for (int kt = 0; kt < 32; kt++) {
        cp_wait<1>();
        __syncthreads();
        const int s = kt & 1;
        const uint32_t kb = base + (uint32_t)s * KSTAGE + kfrag;
        const uint32_t vb = base + V_OFF + (uint32_t)s * 17408u;

        // ---- scores (bf16x3, k16, split-free) ----
        float sf[8][4];
#pragma unroll
        for (int j = 0; j < 8; j++)
#pragma unroll
            for (int r = 0; r < 4; r++) sf[j][r] = 0.0f;

#pragma unroll
        for (int jn = 0; jn < 8; jn++) {
            const uint32_t baddr = kb + (uint32_t)(jn * 8) * KPB;
#pragma unroll
            for (int ka = 0; ka < 5; ka++) {
                uint32_t bh0, bh1, bl0, bl1;
                ldsm4(bh0, bh1, bl0, bl1, baddr + ka * 32);
                mma_bf16(sf[jn], qh[ka], bh0, bh1);
                mma_bf16(sf[jn], qh[ka], bl0, bl1);
                mma_bf16(sf[jn], ql[ka], bh0, bh1);
            }
        }

        // ---- online softmax ----
        float tmax0 = -INFINITY, tmax1 = -INFINITY;
#pragma unroll
        for (int j = 0; j < 8; j++) {
            sf[j][0] *= temp; sf[j][1] *= temp; sf[j][2] *= temp; sf[j][3] *= temp;
            tmax0 = fmaxf(tmax0, fmaxf(sf[j][0], sf[j][1]));
            tmax1 = fmaxf(tmax1, fmaxf(sf[j][2], sf[j][3]));
        }
        tmax0 = fmaxf(tmax0, __shfl_xor_sync(0xffffffffu, tmax0, 1));
        tmax0 = fmaxf(tmax0, __shfl_xor_sync(0xffffffffu, tmax0, 2));
        tmax1 = fmaxf(tmax1, __shfl_xor_sync(0xffffffffu, tmax1, 1));
        tmax1 = fmaxf(tmax1, __shfl_xor_sync(0xffffffffu, tmax1, 2));

        const float mn0 = fmaxf(m0, tmax0), mn1 = fmaxf(m1, tmax1);
        const float sc0 = __expf(m0 - mn0), sc1 = __expf(m1 - mn1);
        m0 = mn0; m1 = mn1;

        float ts0 = 0.f, ts1 = 0.f;
#pragma unroll
        for (int j = 0; j < 8; j++) {
            sf[j][0] = __expf(sf[j][0] - mn0);
            sf[j][1] = __expf(sf[j][1] - mn0);
            sf[j][2] = __expf(sf[j][2] - mn1);
            sf[j][3] = __expf(sf[j][3] - mn1);
            ts0 += sf[j][0] + sf[j][1];
            ts1 += sf[j][2] + sf[j][3];
        }
        ts0 += __shfl_xor_sync(0xffffffffu, ts0, 1);
        ts0 += __shfl_xor_sync(0xffffffffu, ts0, 2);
        ts1 += __shfl_xor_sync(0xffffffffu, ts1, 1);
        ts1 += __shfl_xor_sync(0xffffffffu, ts1, 2);
        l0 = l0 * sc0 + ts0;
        l1 = l1 * sc1 + ts1;

#pragma unroll
        for (int j = 0; j < 8; j++) {
            of[j][0] *= sc0; of[j][1] *= sc0; of[j][2] *= sc1; of[j][3] *= sc1;
        }

        // ---- P to per-warp smem, re-enter as A operand ----
#pragma unroll
        for (int j = 0; j < 8; j++) {
            uint32_t col = (uint32_t)(j * 8 + 2 * qq) * 4;
            sts64(pw + (uint32_t)rquad * VPB + col, sf[j][0], sf[j][1]);
            sts64(pw + (uint32_t)(rquad + 8) * VPB + col, sf[j][2], sf[j][3]);
        }
        __syncwarp();

        // ---- PV (single-pass tf32; V pre-rounded) ----
#pragma unroll
        for (int ka = 0; ka < 8; ka++) {
            uint32_t r0, r1, r2, r3;
            ldsm4(r0, r1, r2, r3, pw + offAP + ka * 32);
            uint32_t ph[4];
            ph[0] = tf32_hi(r0);
            ph[1] = tf32_hi(r1);
            ph[2] = tf32_hi(r2);
            ph[3] = tf32_hi(r3);
#pragma unroll
            for (int jn = 0; jn < 8; jn++) {
                uint32_t v0, v1;
                ldsm2(v0, v1, vb + (uint32_t)(jn * 8 + (lane & 7)) * VPB + ((lane >> 3) & 1) * 16 + ka * 32);
                mma_tf32(of[jn], ph, v0, v1);
            }
        }

        __syncthreads();   // stage s fully consumed before refill
        const int nxt = kt + 2;
        if (nxt < 32) load_tile(nxt, s);
        else cp_commit();
    }

    // ---- epilogue ----
    const float inv0 = 1.0f / l0, inv1 = 1.0f / l1;
    const int t0 = q0 + wid * 16 + rquad;
#pragma unroll
    for (int j = 0; j < 8; j++) {
        const int col = h * 64 + j * 8 + 2 * qq;
        *(float2*)&g_AO[(size_t)(b * Tv + t0) * Dv + col] =
            make_float2(of[j][0] * inv0, of[j][1] * inv0);
        *(float2*)&g_AO[(size_t)(b * Tv + t0 + 8) * Dv + col] =
            make_float2(of[j][2] * inv1, of[j][3] * inv1);
    }
}

// ---------------------------------------------------------------------------
extern "C" void kernel_launch(void* const* d_in, const int* in_sizes, int n_in,
                              void* d_out, int out_size) {
    const float* x   = (const float*)d_in[0];
    const float* Wq  = (const float*)d_in[1];
    const float* bq  = (const float*)d_in[2];
    const float* Wk  = (const float*)d_in[3];
    const float* bk  = (const float*)d_in[4];
    const float* Wv  = (const float*)d_in[5];
    const float* bv  = (const float*)d_in[6];
    const float* Wo  = (const float*)d_in[7];
    const float* bo  = (const float*)d_in[8];
    const float* Wqs = (const float*)d_in[9];
    const float* bqs = (const float*)d_in[10];
    const float* Wks = (const float*)d_in[11];
    const float* bks = (const float*)d_in[12];
    const float* Wvs = (const float*)d_in[13];
    const float* bvs = (const float*)d_in[14];
    const float* temp = (const float*)d_in[15];

    void *gQeH, *gQeL, *gKeH, *gKeL;
    float *gV, *gVt, *gAO;
    cudaGetSymbolAddress(&gQeH, g_QeH);
    cudaGetSymbolAddress(&gQeL, g_QeL);
    cudaGetSymbolAddress(&gKeH, g_KeH);
    cudaGetSymbolAddress(&gKeL, g_KeL);
    cudaGetSymbolAddress((void**)&gV, g_V);
    cudaGetSymbolAddress((void**)&gVt, g_Vt);
    cudaGetSymbolAddress((void**)&gAO, g_AO);

    const int dyn_smem = 4 * STAGE_BYTES;   // 73728
    cudaFuncSetAttribute(gemm_mma<0>, cudaFuncAttributeMaxDynamicSharedMemorySize, dyn_smem);
    cudaFuncSetAttribute(gemm_mma<1>, cudaFuncAttributeMaxDynamicSharedMemorySize, dyn_smem);
    cudaFuncSetAttribute(gemm_mma<2>, cudaFuncAttributeMaxDynamicSharedMemorySize, dyn_smem);
    cudaFuncSetAttribute(gemm_mma<3>, cudaFuncAttributeMaxDynamicSharedMemorySize, dyn_smem);
    cudaFuncSetAttribute(attn_mma, cudaFuncAttributeMaxDynamicSharedMemorySize, ATT_SMEM);

    dim3 ggrid(Dv / 128, Mv / 128);   // (8, 32)
    gemm_mma<1><<<ggrid, 256, dyn_smem>>>(x, Wq, bq, (float*)gQeH, (float*)gQeL);
    gemm_mma<3><<<ggrid, 256, dyn_smem>>>(x, Wk, bk, (float*)gKeH, (float*)gKeL);
    gemm_mma<2><<<ggrid, 256, dyn_smem>>>(x, Wv, bv, gVt, gV);

    int nwarps = Bv * Hv * Tv;                 // 65536
    stp_kernel<<<nwarps / 8, 256>>>(Wqs, bqs, Wks, bks, Wvs, bvs);

    dim3 agrid(Tv / 128, Hv, Bv);              // (16, 16, 2)
    attn_mma<<<agrid, 256, ATT_SMEM>>>(temp);

    gemm_mma<0><<<ggrid, 256, dyn_smem>>>(gAO, Wo, bo, (float*)d_out, nullptr);
}

// round 12
// speedup vs baseline: 3.6050x; 1.0545x over previous
#include <cuda_runtime.h>
#include <cuda_bf16.h>
#include <math.h>
#include <stdint.h>

#define Bv 2
#define Tv 2048
#define Dv 1024
#define Hv 16
#define HDv 64
#define Mv (Bv * Tv)   // 4096

// Scratch (allocation-free rule: __device__ globals; zero-initialized at load)
__device__ __nv_bfloat16 g_QeH[Bv * Hv * Tv * 80];  // bf16-hi of q / q_stp (cols 64-66)
__device__ __nv_bfloat16 g_QeL[Bv * Hv * Tv * 80];  // bf16-lo residual
__device__ __nv_bfloat16 g_KeH[Bv * Hv * Tv * 80];  // bf16-hi of k / cross_kv
__device__ __nv_bfloat16 g_KeL[Bv * Hv * Tv * 80];  // bf16-lo residual
__device__ float g_V  [Bv * Hv * Tv * HDv]; // [b,h,t,hd] full precision (for stp)
__device__ float g_Vt [Bv * Hv * HDv * Tv]; // [b,h,hd,t] tf32-rounded (for PV mma)
__device__ float g_AO [Bv * Tv * Dv];       // attention out, [b,t,h*HD+hd]

// ======================= base-ISA helpers (sm_80-class) =====================
__device__ __forceinline__ uint32_t smem_u32(const void* p) {
    uint32_t a;
    asm("{ .reg .u64 t; cvta.to.shared.u64 t, %1; cvt.u32.u64 %0, t; }" : "=r"(a) : "l"(p));
    return a;
}
__device__ __forceinline__ void cp16(uint32_t dst, const void* src) {
    asm volatile("cp.async.cg.shared.global [%0], [%1], 16;" :: "r"(dst), "l"(src) : "memory");
}
__device__ __forceinline__ void cp_commit() {
    asm volatile("cp.async.commit_group;" ::: "memory");
}
template <int N>
__device__ __forceinline__ void cp_wait() {
    asm volatile("cp.async.wait_group %0;" :: "n"(N) : "memory");
}
__device__ __forceinline__ void ldsm4(uint32_t& r0, uint32_t& r1, uint32_t& r2, uint32_t& r3,
                                      uint32_t addr) {
    asm volatile("ldmatrix.sync.aligned.m8n8.x4.shared.b16 {%0,%1,%2,%3}, [%4];"
                 : "=r"(r0), "=r"(r1), "=r"(r2), "=r"(r3) : "r"(addr));
}
__device__ __forceinline__ void ldsm2(uint32_t& r0, uint32_t& r1, uint32_t addr) {
    asm volatile("ldmatrix.sync.aligned.m8n8.x2.shared.b16 {%0,%1}, [%2];"
                 : "=r"(r0), "=r"(r1) : "r"(addr));
}
__device__ __forceinline__ void sts64(uint32_t addr, float x, float y) {
    asm volatile("st.shared.v2.f32 [%0], {%1,%2};" :: "r"(addr), "f"(x), "f"(y) : "memory");
}
__device__ __forceinline__ void mma_tf32(float* d, const uint32_t* a, uint32_t b0, uint32_t b1) {
    asm volatile(
        "mma.sync.aligned.m16n8k8.row.col.f32.tf32.tf32.f32 "
        "{%0,%1,%2,%3}, {%4,%5,%6,%7}, {%8,%9}, {%0,%1,%2,%3};"
        : "+f"(d[0]), "+f"(d[1]), "+f"(d[2]), "+f"(d[3])
        : "r"(a[0]), "r"(a[1]), "r"(a[2]), "r"(a[3]), "r"(b0), "r"(b1));
}
__device__ __forceinline__ void mma_bf16(float* d, const uint32_t* a, uint32_t b0, uint32_t b1) {
    asm volatile(
        "mma.sync.aligned.m16n8k16.row.col.f32.bf16.bf16.f32 "
        "{%0,%1,%2,%3}, {%4,%5,%6,%7}, {%8,%9}, {%0,%1,%2,%3};"
        : "+f"(d[0]), "+f"(d[1]), "+f"(d[2]), "+f"(d[3])
        : "r"(a[0]), "r"(a[1]), "r"(a[2]), "r"(a[3]), "r"(b0), "r"(b1));
}
// 3xTF32 split: hi = tf32(x), lo = tf32(x - hi)
__device__ __forceinline__ void split_tf32(uint32_t raw, uint32_t& hi, uint32_t& lo) {
    float f = __uint_as_float(raw);
    asm("cvt.rna.tf32.f32 %0, %1;" : "=r"(hi) : "f"(f));
    float r = f - __uint_as_float(hi);
    asm("cvt.rna.tf32.f32 %0, %1;" : "=r"(lo) : "f"(r));
}
__device__ __forceinline__ uint32_t tf32_hi(uint32_t raw) {
    uint32_t hi;
    asm("cvt.rna.tf32.f32 %0, %1;" : "=r"(hi) : "f"(__uint_as_float(raw)));
    return hi;
}
__device__ __forceinline__ uint32_t tf32_hif(float f) {
    uint32_t hi;
    asm("cvt.rna.tf32.f32 %0, %1;" : "=r"(hi) : "f"(f));
    return hi;
}
// bf16 hi/lo split of an fp32
__device__ __forceinline__ void split_bf16(float f, __nv_bfloat16& h, __nv_bfloat16& l) {
    h = __float2bfloat16_rn(f);
    l = __float2bfloat16_rn(f - __bfloat162float(h));
}

// ---------------------------------------------------------------------------
// 3xTF32 mma.sync GEMM: C[m,n] = sum_k X[m,k] * W[n,k] + bias[n]
// MODE 0: plain row-major. MODE 1: Q head-split pitch-80 bf16 hi/lo planes.
// MODE 2: V dual-write (g_Vt transposed tf32-rounded, g_V full head-split).
// MODE 3: K head-split pitch-80 bf16 hi/lo planes.
// ---------------------------------------------------------------------------
#define PITCH 36
#define PITCHB (PITCH * 4)           // 144 bytes
#define STAGE_BYTES (128 * PITCHB)   // 18432
#define KCH 32
#define NSTEP (1024 / KCH)           // 32

template <int MODE>
__global__ __launch_bounds__(256) void gemm_mma(const float* __restrict__ X,
                                                const float* __restrict__ W,
                                                const float* __restrict__ bias,
                                                float* __restrict__ out,
                                                float* __restrict__ out2) {
    extern __shared__ char dsm[];
    const uint32_t sbase = smem_u32(dsm);
    const int K = 1024;
    const int n0 = blockIdx.x * 128;
    const int m0 = blockIdx.y * 128;
    const int tid = threadIdx.x;
    const int lane = tid & 31;
    const int wid = tid >> 5;
    const int wm = wid >> 2;
    const int wn = wid & 3;

    uint32_t Ab[2], Wb[2];
    Ab[0] = sbase;                     Wb[0] = sbase + STAGE_BYTES;
    Ab[1] = sbase + 2 * STAGE_BYTES;   Wb[1] = sbase + 3 * STAGE_BYTES;

    const uint32_t offA = ((lane & 7) + ((lane >> 3) & 1) * 8) * PITCHB + ((lane >> 4) & 1) * 16;
    const uint32_t offB = (lane & 7) * PITCHB + ((lane >> 3) & 1) * 16;
    const uint32_t aWarp = (uint32_t)(wm * 64) * PITCHB + offA;
    const uint32_t bWarp = (uint32_t)(wn * 32) * PITCHB + offB;

    const int lrow0 = tid >> 3;
    const int lc4 = (tid & 7) * 16;

    float acc[4][4][4];
#pragma unroll
    for (int i = 0; i < 4; i++)
#pragma unroll
        for (int j = 0; j < 4; j++)
#pragma unroll
            for (int r = 0; r < 4; r++) acc[i][j][r] = 0.0f;

#pragma unroll
    for (int s = 0; s < 2; s++) {
        const int k0 = s * KCH;
#pragma unroll
        for (int it = 0; it < 4; it++) {
            int row = lrow0 + it * 32;
            cp16(Ab[s] + (uint32_t)row * PITCHB + lc4, &X[(size_t)(m0 + row) * K + k0] + (lc4 >> 2));
            cp16(Wb[s] + (uint32_t)row * PITCHB + lc4, &W[(size_t)(n0 + row) * K + k0] + (lc4 >> 2));
        }
        cp_commit();
    }

    for (int c = 0; c < NSTEP; c++) {
        cp_wait<1>();
        __syncthreads();
        const int s = c & 1;
        const uint32_t Abase = Ab[s] + aWarp;
        const uint32_t Bbase = Wb[s] + bWarp;

#pragma unroll
        for (int ka = 0; ka < 4; ka++) {
            uint32_t bh0[4], bh1[4], bl0[4], bl1[4];
#pragma unroll
            for (int jn = 0; jn < 4; jn++) {
                uint32_t r0, r1;
                ldsm2(r0, r1, Bbase + (uint32_t)(jn * 8) * PITCHB + ka * 32);
                split_tf32(r0, bh0[jn], bl0[jn]);
                split_tf32(r1, bh1[jn], bl1[jn]);
            }
#pragma unroll
            for (int i = 0; i < 4; i++) {
                uint32_t r0, r1, r2, r3;
                ldsm4(r0, r1, r2, r3, Abase + (uint32_t)(i * 16) * PITCHB + ka * 32);
                uint32_t ah[4], al[4];
                split_tf32(r0, ah[0], al[0]);
                split_tf32(r1, ah[1], al[1]);
                split_tf32(r2, ah[2], al[2]);
                split_tf32(r3, ah[3], al[3]);
#pragma unroll
                for (int jn = 0; jn < 4; jn++) {
                    mma_tf32(acc[i][jn], ah, bh0[jn], bh1[jn]);
                    mma_tf32(acc[i][jn], ah, bl0[jn], bl1[jn]);
                    mma_tf32(acc[i][jn], al, bh0[jn], bh1[jn]);
                }
            }
        }
        __syncthreads();

        const int nxt = c + 2;
        if (nxt < NSTEP) {
            const int k0 = nxt * KCH;
#pragma unroll
            for (int it = 0; it < 4; it++) {
                int row = lrow0 + it * 32;
                cp16(Ab[s] + (uint32_t)row * PITCHB + lc4, &X[(size_t)(m0 + row) * K + k0] + (lc4 >> 2));
                cp16(Wb[s] + (uint32_t)row * PITCHB + lc4, &W[(size_t)(n0 + row) * K + k0] + (lc4 >> 2));
            }
        }
        cp_commit();
    }

#pragma unroll
    for (int i = 0; i < 4; i++) {
        const int mlo = m0 + wm * 64 + i * 16 + (lane >> 2);
#pragma unroll
        for (int jn = 0; jn < 4; jn++) {
            const int nb = n0 + wn * 32 + jn * 8 + (lane & 3) * 2;
            const float2 bb = *(const float2*)&bias[nb];
            float2 v0 = make_float2(acc[i][jn][0] + bb.x, acc[i][jn][1] + bb.y);
            float2 v1 = make_float2(acc[i][jn][2] + bb.x, acc[i][jn][3] + bb.y);
#pragma unroll
            for (int u = 0; u < 2; u++) {
                const int m = mlo + u * 8;
                const float2 v = (u == 0) ? v0 : v1;
                if (MODE == 0) {
                    *(float2*)&out[(size_t)m * Dv + nb] = v;
                } else if (MODE == 1 || MODE == 3) {
                    // bf16 hi/lo planes, pitch 80
                    int b = m >> 11, t = m & 2047;
                    int h = nb >> 6, hd = nb & 63;
                    size_t idx = ((size_t)(b * Hv + h) * Tv + t) * 80 + hd;
                    __nv_bfloat16 hx, lx, hy, ly;
                    split_bf16(v.x, hx, lx);
                    split_bf16(v.y, hy, ly);
                    __nv_bfloat16* oh = (__nv_bfloat16*)out;
                    __nv_bfloat16* ol = (__nv_bfloat16*)out2;
                    *(__nv_bfloat162*)&oh[idx] = __nv_bfloat162(hx, hy);
                    *(__nv_bfloat162*)&ol[idx] = __nv_bfloat162(lx, ly);
                } else {  // MODE 2: V dual-write
                    int b = m >> 11, t = m & 2047;
                    int h = nb >> 6, hd = nb & 63;
                    size_t vt = ((size_t)((b * Hv + h) * HDv + hd)) * Tv + t;
                    out[vt] = __uint_as_float(tf32_hif(v.x));
                    out[vt + Tv] = __uint_as_float(tf32_hif(v.y));
                    *(float2*)&out2[(((size_t)(b * Hv + h) * Tv) + t) * HDv + hd] = v;
                }
            }
        }
    }
}

// ---------------------------------------------------------------------------
// STP: per (b,h,t) row, compute q_stp[3] and cross(k3, v3)[3]; write bf16
// hi/lo into cols 64-71 of the Q / K planes.
// ---------------------------------------------------------------------------
__global__ __launch_bounds__(256) void stp_kernel(const float* __restrict__ Wqs,
                                                  const float* __restrict__ bqs,
                                                  const float* __restrict__ Wks,
                                                  const float* __restrict__ bks,
                                                  const float* __restrict__ Wvs,
                                                  const float* __restrict__ bvs) {
    int warp = (blockIdx.x * blockDim.x + threadIdx.x) >> 5;
    int lane = threadIdx.x & 31;
    if (warp >= Bv * Hv * Tv) return;

    const __nv_bfloat16* qh = g_QeH + (size_t)warp * 80;
    const __nv_bfloat16* ql = g_QeL + (size_t)warp * 80;
    const __nv_bfloat16* kh = g_KeH + (size_t)warp * 80;
    const __nv_bfloat16* kl = g_KeL + (size_t)warp * 80;
    const float* v = g_V + (size_t)warp * HDv;

    float q0 = __bfloat162float(qh[lane]) + __bfloat162float(ql[lane]);
    float q1 = __bfloat162float(qh[lane + 32]) + __bfloat162float(ql[lane + 32]);
    float k0 = __bfloat162float(kh[lane]) + __bfloat162float(kl[lane]);
    float k1 = __bfloat162float(kh[lane + 32]) + __bfloat162float(kl[lane + 32]);
    float v0 = v[lane], v1 = v[lane + 32];

    float qs[3], k3[3], v3[3];
#pragma unroll
    for (int c = 0; c < 3; c++) {
        float pq = q0 * Wqs[c * HDv + lane] + q1 * Wqs[c * HDv + lane + 32];
        float pk = k0 * Wks[c * HDv + lane] + k1 * Wks[c * HDv + lane + 32];
        float pv = v0 * Wvs[c * HDv + lane] + v1 * Wvs[c * HDv + lane + 32];
#pragma unroll
        for (int o = 16; o > 0; o >>= 1) {
            pq += __shfl_xor_sync(0xffffffffu, pq, o);
            pk += __shfl_xor_sync(0xffffffffu, pk, o);
            pv += __shfl_xor_sync(0xffffffffu, pv, o);
        }
        qs[c] = pq + bqs[c];
        k3[c] = pk + bks[c];
        v3[c] = pv + bvs[c];
    }

    if (lane == 0) {
        float cr[3];
        cr[0] = k3[1] * v3[2] - k3[2] * v3[1];
        cr[1] = k3[2] * v3[0] - k3[0] * v3[2];
        cr[2] = k3[0] * v3[1] - k3[1] * v3[0];
        __nv_bfloat16 z = __float2bfloat16_rn(0.f);
        __nv_bfloat16 qhv[8], qlv[8], khv[8], klv[8];
#pragma unroll
        for (int c = 0; c < 8; c++) { qhv[c] = z; qlv[c] = z; khv[c] = z; klv[c] = z; }
#pragma unroll
        for (int c = 0; c < 3; c++) {
            split_bf16(qs[c], qhv[c], qlv[c]);
            split_bf16(cr[c], khv[c], klv[c]);
        }
        *(float4*)&g_QeH[(size_t)warp * 80 + 64] = *(float4*)qhv;
        *(float4*)&g_QeL[(size_t)warp * 80 + 64] = *(float4*)qlv;
        *(float4*)&g_KeH[(size_t)warp * 80 + 64] = *(float4*)khv;
        *(float4*)&g_KeL[(size_t)warp * 80 + 64] = *(float4*)klv;
    }
}

// ---------------------------------------------------------------------------
// mma.sync flash attention. CTA = 256 q-rows of one head; 16 warps x 16 rows
// (4 warps/SMSP for latency hiding). 3-stage K/V ring, ONE barrier per tile:
// loads for kt+2 issue right after the barrier (stage consumed at kt-1).
// Scores: bf16x3 m16n8k16 over 80 dims; K hi/lo via lane-mapped ldsm4.
// PV: single-pass tf32 (V pre-rounded).
// Smem: K 3x22528 [0,67584), V 3x17408 [67584,119808), P 16x4352 [119808,189440).
// ---------------------------------------------------------------------------
#define KPB 176   // K/Q bf16 smem pitch bytes (11x16B; conflict-free)
#define VPB 272   // V/P smem pitch bytes (68 floats; conflict-free)
#define KSTAGE 22528u
#define KLO_OFF 11264u
#define V_OFF 67584u
#define P_OFF 119808u
#define QLO_STAGE 45056u
#define ATT_SMEM 189440

__global__ __launch_bounds__(512, 1) void attn_mma(const float* __restrict__ temp_p) {
    extern __shared__ char dsm[];
    const uint32_t base = smem_u32(dsm);
    const int b = blockIdx.z, h = blockIdx.y;
    const int q0 = blockIdx.x * 256;
    const int tid = threadIdx.x, lane = tid & 31, wid = tid >> 5;
    const float temp = *temp_p;

    const __nv_bfloat16* QeH = g_QeH + ((size_t)(b * Hv + h) * Tv + q0) * 80;
    const __nv_bfloat16* QeL = g_QeL + ((size_t)(b * Hv + h) * Tv + q0) * 80;
    const __nv_bfloat16* KeH = g_KeH + (size_t)(b * Hv + h) * Tv * 80;
    const __nv_bfloat16* KeL = g_KeL + (size_t)(b * Hv + h) * Tv * 80;
    const float* Vt = g_Vt + (size_t)(b * Hv + h) * HDv * Tv;

    // ---- stage Q hi/lo (borrow K+V ring region): hi [0,45056), lo [45056,90112) ----
#pragma unroll
    for (int i = 0; i < 10; i++) {
        int idx = tid + i * 512;          // 0..5119
        int plane = idx >= 2560;
        int rem = idx - plane * 2560;
        int row = rem / 10, c = rem % 10;
        const __nv_bfloat16* src = plane ? QeL : QeH;
        cp16(base + (uint32_t)plane * QLO_STAGE + (uint32_t)row * KPB + c * 16,
             src + (size_t)row * 80 + c * 8);
    }
    cp_commit();
    cp_wait<0>();
    __syncthreads();

    uint32_t qh[5][4], ql[5][4];
    {
        const uint32_t qa = base + (uint32_t)(wid * 16) * KPB +
            ((lane & 7) + ((lane >> 3) & 1) * 8) * KPB + ((lane >> 4) & 1) * 16;
#pragma unroll
        for (int ka = 0; ka < 5; ka++) {
            ldsm4(qh[ka][0], qh[ka][1], qh[ka][2], qh[ka][3], qa + ka * 32);
            ldsm4(ql[ka][0], ql[ka][1], ql[ka][2], ql[ka][3], qa + QLO_STAGE + ka * 32);
        }
    }
    __syncthreads();   // Q staging area free before K/V loads

    float of[8][4];
#pragma unroll
    for (int j = 0; j < 8; j++)
#pragma unroll
        for (int r = 0; r < 4; r++) of[j][r] = 0.0f;
    float m0 = -INFINITY, m1 = -INFINITY, l0 = 0.f, l1 = 0.f;

    auto load_tile = [&](int kt, int s) {
        uint32_t kb = base + (uint32_t)s * KSTAGE;
#pragma unroll
        for (int i = 0; i < 3; i++) {
            int idx = tid + i * 512;       // 0..1535, valid < 1280
            if (idx < 1280) {
                int plane = idx >= 640;
                int rem = idx - plane * 640;
                int row = rem / 10, c = rem % 10;
                const __nv_bfloat16* src = plane ? KeL : KeH;
                cp16(kb + (uint32_t)plane * KLO_OFF + (uint32_t)row * KPB + c * 16,
                     src + (size_t)(kt * 64 + row) * 80 + c * 8);
            }
        }
        uint32_t vb = base + V_OFF + (uint32_t)s * 17408u;
#pragma unroll
        for (int i = 0; i < 2; i++) {
            int idx = tid + i * 512;       // 0..1023
            int row = idx >> 4, c = idx & 15;
            cp16(vb + (uint32_t)row * VPB + c * 16, Vt + (size_t)row * Tv + kt * 64 + c * 4);
        }
    };

    load_tile(0, 0);
    cp_commit();
    load_tile(1, 1);
    cp_commit();

    const uint32_t pw = base + P_OFF + (uint32_t)wid * 4352u;
    const uint32_t offAP = ((lane & 7) + ((lane >> 3) & 1) * 8) * VPB + ((lane >> 4) & 1) * 16;
    // K fragment per-lane offset: lanes 0-15 hi plane, 16-31 lo plane.
    const uint32_t kfrag = ((lane >> 4) & 1) * KLO_OFF + (lane & 7) * KPB + ((lane >> 3) & 1) * 16;
    const int rquad = lane >> 2, qq = lane & 3;

    for (int kt = 0; kt < 32; kt++) {
        cp_wait<1>();          // tile kt resident
        __syncthreads();       // all warps done with tile kt-1 (stage (kt+2)%3 free)

        const int nxt = kt + 2;
        if (nxt < 32) load_tile(nxt, nxt % 3);
        cp_commit();

        const int s = kt % 3;
        const uint32_t kb = base + (uint32_t)s * KSTAGE + kfrag;
        const uint32_t vb = base + V_OFF + (uint32_t)s * 17408u;

        // ---- scores (bf16x3, k16, split-free) ----
        float sf[8][4];
#pragma unroll
        for (int j = 0; j < 8; j++)
#pragma unroll
            for (int r = 0; r < 4; r++) sf[j][r] = 0.0f;

#pragma unroll
        for (int jn = 0; jn < 8; jn++) {
            const uint32_t baddr = kb + (uint32_t)(jn * 8) * KPB;
#pragma unroll
            for (int ka = 0; ka < 5; ka++) {
                uint32_t bh0, bh1, bl0, bl1;
                ldsm4(bh0, bh1, bl0, bl1, baddr + ka * 32);
                mma_bf16(sf[jn], qh[ka], bh0, bh1);
                mma_bf16(sf[jn], qh[ka], bl0, bl1);
                mma_bf16(sf[jn], ql[ka], bh0, bh1);
            }
        }

        // ---- online softmax ----
        float tmax0 = -INFINITY, tmax1 = -INFINITY;
#pragma unroll
        for (int j = 0; j < 8; j++) {
            sf[j][0] *= temp; sf[j][1] *= temp; sf[j][2] *= temp; sf[j][3] *= temp;
            tmax0 = fmaxf(tmax0, fmaxf(sf[j][0], sf[j][1]));
            tmax1 = fmaxf(tmax1, fmaxf(sf[j][2], sf[j][3]));
        }
        tmax0 = fmaxf(tmax0, __shfl_xor_sync(0xffffffffu, tmax0, 1));
        tmax0 = fmaxf(tmax0, __shfl_xor_sync(0xffffffffu, tmax0, 2));
        tmax1 = fmaxf(tmax1, __shfl_xor_sync(0xffffffffu, tmax1, 1));
        tmax1 = fmaxf(tmax1, __shfl_xor_sync(0xffffffffu, tmax1, 2));

        const float mn0 = fmaxf(m0, tmax0), mn1 = fmaxf(m1, tmax1);
        const float sc0 = __expf(m0 - mn0), sc1 = __expf(m1 - mn1);
        m0 = mn0; m1 = mn1;

        float ts0 = 0.f, ts1 = 0.f;
#pragma unroll
        for (int j = 0; j < 8; j++) {
            sf[j][0] = __expf(sf[j][0] - mn0);
            sf[j][1] = __expf(sf[j][1] - mn0);
            sf[j][2] = __expf(sf[j][2] - mn1);
            sf[j][3] = __expf(sf[j][3] - mn1);
            ts0 += sf[j][0] + sf[j][1];
            ts1 += sf[j][2] + sf[j][3];
        }
        ts0 += __shfl_xor_sync(0xffffffffu, ts0, 1);
        ts0 += __shfl_xor_sync(0xffffffffu, ts0, 2);
        ts1 += __shfl_xor_sync(0xffffffffu, ts1, 1);
        ts1 += __shfl_xor_sync(0xffffffffu, ts1, 2);
        l0 = l0 * sc0 + ts0;
        l1 = l1 * sc1 + ts1;

#pragma unroll
        for (int j = 0; j < 8; j++) {
            of[j][0] *= sc0; of[j][1] *= sc0; of[j][2] *= sc1; of[j][3] *= sc1;
        }

        // ---- P to per-warp smem, re-enter as A operand ----
#pragma unroll
        for (int j = 0; j < 8; j++) {
            uint32_t col = (uint32_t)(j * 8 + 2 * qq) * 4;
            sts64(pw + (uint32_t)rquad * VPB + col, sf[j][0], sf[j][1]);
            sts64(pw + (uint32_t)(rquad + 8) * VPB + col, sf[j][2], sf[j][3]);
        }
        __syncwarp();

        // ---- PV (single-pass tf32; V pre-rounded) ----
#pragma unroll
        for (int ka = 0; ka < 8; ka++) {
            uint32_t r0, r1, r2, r3;
            ldsm4(r0, r1, r2, r3, pw + offAP + ka * 32);
            uint32_t ph[4];
            ph[0] = tf32_hi(r0);
            ph[1] = tf32_hi(r1);
            ph[2] = tf32_hi(r2);
            ph[3] = tf32_hi(r3);
#pragma unroll
            for (int jn = 0; jn < 8; jn++) {
                uint32_t v0, v1;
                ldsm2(v0, v1, vb + (uint32_t)(jn * 8 + (lane & 7)) * VPB + ((lane >> 3) & 1) * 16 + ka * 32);
                mma_tf32(of[jn], ph, v0, v1);
            }
        }
        // no trailing barrier: next iteration's top barrier orders stage reuse
    }

    // ---- epilogue ----
    const float inv0 = 1.0f / l0, inv1 = 1.0f / l1;
    const int t0 = q0 + wid * 16 + rquad;
#pragma unroll
    for (int j = 0; j < 8; j++) {
        const int col = h * 64 + j * 8 + 2 * qq;
        *(float2*)&g_AO[(size_t)(b * Tv + t0) * Dv + col] =
            make_float2(of[j][0] * inv0, of[j][1] * inv0);
        *(float2*)&g_AO[(size_t)(b * Tv + t0 + 8) * Dv + col] =
            make_float2(of[j][2] * inv1, of[j][3] * inv1);
    }
}

// ---------------------------------------------------------------------------
extern "C" void kernel_launch(void* const* d_in, const int* in_sizes, int n_in,
                              void* d_out, int out_size) {
    const float* x   = (const float*)d_in[0];
    const float* Wq  = (const float*)d_in[1];
    const float* bq  = (const float*)d_in[2];
    const float* Wk  = (const float*)d_in[3];
    const float* bk  = (const float*)d_in[4];
    const float* Wv  = (const float*)d_in[5];
    const float* bv  = (const float*)d_in[6];
    const float* Wo  = (const float*)d_in[7];
    const float* bo  = (const float*)d_in[8];
    const float* Wqs = (const float*)d_in[9];
    const float* bqs = (const float*)d_in[10];
    const float* Wks = (const float*)d_in[11];
    const float* bks = (const float*)d_in[12];
    const float* Wvs = (const float*)d_in[13];
    const float* bvs = (const float*)d_in[14];
    const float* temp = (const float*)d_in[15];

    void *gQeH, *gQeL, *gKeH, *gKeL;
    float *gV, *gVt, *gAO;
    cudaGetSymbolAddress(&gQeH, g_QeH);
    cudaGetSymbolAddress(&gQeL, g_QeL);
    cudaGetSymbolAddress(&gKeH, g_KeH);
    cudaGetSymbolAddress(&gKeL, g_KeL);
    cudaGetSymbolAddress((void**)&gV, g_V);
    cudaGetSymbolAddress((void**)&gVt, g_Vt);
    cudaGetSymbolAddress((void**)&gAO, g_AO);

    const int dyn_smem = 4 * STAGE_BYTES;   // 73728
    cudaFuncSetAttribute(gemm_mma<0>, cudaFuncAttributeMaxDynamicSharedMemorySize, dyn_smem);
    cudaFuncSetAttribute(gemm_mma<1>, cudaFuncAttributeMaxDynamicSharedMemorySize, dyn_smem);
    cudaFuncSetAttribute(gemm_mma<2>, cudaFuncAttributeMaxDynamicSharedMemorySize, dyn_smem);
    cudaFuncSetAttribute(gemm_mma<3>, cudaFuncAttributeMaxDynamicSharedMemorySize, dyn_smem);
    cudaFuncSetAttribute(attn_mma, cudaFuncAttributeMaxDynamicSharedMemorySize, ATT_SMEM);

    dim3 ggrid(Dv / 128, Mv / 128);   // (8, 32)
    gemm_mma<1><<<ggrid, 256, dyn_smem>>>(x, Wq, bq, (float*)gQeH, (float*)gQeL);
    gemm_mma<3><<<ggrid, 256, dyn_smem>>>(x, Wk, bk, (float*)gKeH, (float*)gKeL);
    gemm_mma<2><<<ggrid, 256, dyn_smem>>>(x, Wv, bv, gVt, gV);

    int nwarps = Bv * Hv * Tv;                 // 65536
    stp_kernel<<<nwarps / 8, 256>>>(Wqs, bqs, Wks, bks, Wvs, bvs);

    dim3 agrid(Tv / 256, Hv, Bv);              // (8, 16, 2)
    attn_mma<<<agrid, 512, ATT_SMEM>>>(temp);

    gemm_mma<0><<<ggrid, 256, dyn_smem>>>(gAO, Wo, bo, (float*)d_out, nullptr);
}